// round 1
// baseline (speedup 1.0000x reference)
#include <cuda_runtime.h>
#include <cuda_bf16.h>
#include <math.h>

// Problem constants
#define BATCH 4
#define SEQ   1024
#define DMODEL 1024
#define NHEAD 16
#define HDIM  64
#define FFDIM 4096
#define MS    (BATCH*SEQ)        // 4096 rows
#define EPS   1e-5f

// ---------------- scratch (device globals; no allocation allowed) -------------
__device__ float g_qkv[MS * 3 * DMODEL];            // [B,S,3D]
__device__ float g_probs[BATCH * NHEAD * SEQ * SEQ]; // scores -> probs (in place)
__device__ float g_ctx[MS * DMODEL];
__device__ float g_attnout[MS * DMODEL];
__device__ float g_x[MS * DMODEL];                   // after LN1
__device__ float g_ffh[MS * FFDIM];
__device__ float g_ffo[MS * DMODEL];

// ---------------- generic batched SGEMM:  C[z,m,n] = sum_k A[z,m,k]*B[z,n,k] --
// element addressing:
//   A + (z/HB)*aB1 + (z%HB)*aB2 + m*aRS + k*aCS
//   B + (z/HB)*bB1 + (z%HB)*bB2 + n*bRS + k*bCS
//   C + (z/HB)*cB1 + (z%HB)*cB2 + m*cRS + n           (n contiguous)
// EPI: 0 = +biasvec[n]; 1 = gelu(acc+biasvec[n]); 2 = acc*scale + biasmat; 3 = none
#define BM 128
#define BN 128
#define BK 8
#define TM 8
#define TN 8

__global__ void __launch_bounds__(256)
gemm_kernel(const float* __restrict__ A, const float* __restrict__ B,
            float* __restrict__ C,
            int M, int N, int K,
            long aRS, long aCS, long aB1, long aB2,
            long bRS, long bCS, long bB1, long bB2,
            long cRS, long cB1, long cB2,
            int HB,
            const float* __restrict__ bias, long biasB2, long biasRS,
            float scale, int epi)
{
    __shared__ float As[BK][BM];
    __shared__ float Bs[BK][BN];

    const int tid = threadIdx.x;
    const int tx = tid & 15;       // 0..15  (cols)
    const int ty = tid >> 4;       // 0..15  (rows)
    const int m0 = blockIdx.y * BM;
    const int n0 = blockIdx.x * BN;
    const int z  = blockIdx.z;
    const int zb = z / HB;
    const int zh = z % HB;

    const float* Az = A + (long)zb * aB1 + (long)zh * aB2;
    const float* Bz = B + (long)zb * bB1 + (long)zh * bB2;
    float*       Cz = C + (long)zb * cB1 + (long)zh * cB2;

    float acc[TM][TN];
    #pragma unroll
    for (int i = 0; i < TM; i++)
        #pragma unroll
        for (int j = 0; j < TN; j++) acc[i][j] = 0.f;

    // loader mapping: e in [0,1024), m=e/8, kk=e%8; each thread loads e=tid*4+t
    const int lm = tid >> 1;              // e/8 with e=tid*4+t (t<4): row index
    const int lk0 = (tid & 1) * 4;        // base kk

    for (int k0 = 0; k0 < K; k0 += BK) {
        // load A tile
        #pragma unroll
        for (int t = 0; t < 4; t++) {
            int kk = lk0 + t;
            int mr = m0 + lm;
            int kr = k0 + kk;
            float v = 0.f;
            if (mr < M && kr < K) v = Az[(long)mr * aRS + (long)kr * aCS];
            As[kk][lm] = v;
        }
        // load B tile
        #pragma unroll
        for (int t = 0; t < 4; t++) {
            int kk = lk0 + t;
            int nr = n0 + lm;
            int kr = k0 + kk;
            float v = 0.f;
            if (nr < N && kr < K) v = Bz[(long)nr * bRS + (long)kr * bCS];
            Bs[kk][lm] = v;
        }
        __syncthreads();

        #pragma unroll
        for (int kk = 0; kk < BK; kk++) {
            float a[TM], b[TN];
            float4 a0 = *(const float4*)&As[kk][ty * TM];
            float4 a1 = *(const float4*)&As[kk][ty * TM + 4];
            float4 b0 = *(const float4*)&Bs[kk][tx * TN];
            float4 b1 = *(const float4*)&Bs[kk][tx * TN + 4];
            a[0]=a0.x; a[1]=a0.y; a[2]=a0.z; a[3]=a0.w;
            a[4]=a1.x; a[5]=a1.y; a[6]=a1.z; a[7]=a1.w;
            b[0]=b0.x; b[1]=b0.y; b[2]=b0.z; b[3]=b0.w;
            b[4]=b1.x; b[5]=b1.y; b[6]=b1.z; b[7]=b1.w;
            #pragma unroll
            for (int i = 0; i < TM; i++)
                #pragma unroll
                for (int j = 0; j < TN; j++)
                    acc[i][j] = fmaf(a[i], b[j], acc[i][j]);
        }
        __syncthreads();
    }

    // epilogue
    #pragma unroll
    for (int i = 0; i < TM; i++) {
        int row = m0 + ty * TM + i;
        if (row >= M) continue;
        #pragma unroll
        for (int j = 0; j < TN; j++) {
            int col = n0 + tx * TN + j;
            if (col >= N) continue;
            float v = acc[i][j];
            if (epi == 0) {
                v += bias[col];
            } else if (epi == 1) {
                v += bias[col];
                v = 0.5f * v * (1.0f + erff(v * 0.70710678118654752f));
            } else if (epi == 2) {
                v = v * scale + bias[(long)zh * biasB2 + (long)row * biasRS + col];
            }
            Cz[(long)row * cRS + col] = v;
        }
    }
}

// ---------------- row softmax over 1024 elements, one block per row ----------
__device__ __forceinline__ float warpMax(float v) {
    #pragma unroll
    for (int o = 16; o; o >>= 1) v = fmaxf(v, __shfl_xor_sync(0xffffffffu, v, o));
    return v;
}
__device__ __forceinline__ float warpSum(float v) {
    #pragma unroll
    for (int o = 16; o; o >>= 1) v += __shfl_xor_sync(0xffffffffu, v, o);
    return v;
}

__global__ void __launch_bounds__(256) softmax_kernel(float* __restrict__ probs)
{
    float* row = probs + (size_t)blockIdx.x * SEQ;
    const int tid = threadIdx.x;
    __shared__ float sh[8];

    float x[4];
    #pragma unroll
    for (int j = 0; j < 4; j++) x[j] = row[tid + 256 * j];

    float m = fmaxf(fmaxf(x[0], x[1]), fmaxf(x[2], x[3]));
    m = warpMax(m);
    if ((tid & 31) == 0) sh[tid >> 5] = m;
    __syncthreads();
    if (tid < 32) {
        float t = (tid < 8) ? sh[tid] : -INFINITY;
        t = warpMax(t);
        if (tid == 0) sh[0] = t;
    }
    __syncthreads();
    m = sh[0];
    __syncthreads();

    float s = 0.f;
    #pragma unroll
    for (int j = 0; j < 4; j++) { x[j] = __expf(x[j] - m); s += x[j]; }
    s = warpSum(s);
    if ((tid & 31) == 0) sh[tid >> 5] = s;
    __syncthreads();
    if (tid < 32) {
        float t = (tid < 8) ? sh[tid] : 0.f;
        t = warpSum(t);
        if (tid == 0) sh[0] = t;
    }
    __syncthreads();
    float inv = 1.0f / sh[0];
    #pragma unroll
    for (int j = 0; j < 4; j++) row[tid + 256 * j] = x[j] * inv;
}

// ---------------- residual add + LayerNorm over D=1024, one block per row ----
__global__ void __launch_bounds__(256)
add_ln_kernel(const float* __restrict__ a, const float* __restrict__ b,
              const float* __restrict__ gamma, const float* __restrict__ beta,
              float* __restrict__ out)
{
    const size_t base = (size_t)blockIdx.x * DMODEL;
    const int tid = threadIdx.x;
    __shared__ float sh[8];

    float v[4];
    #pragma unroll
    for (int j = 0; j < 4; j++) {
        int col = tid + 256 * j;
        v[j] = a[base + col] + b[base + col];
    }
    // mean
    float s = v[0] + v[1] + v[2] + v[3];
    s = warpSum(s);
    if ((tid & 31) == 0) sh[tid >> 5] = s;
    __syncthreads();
    if (tid < 32) {
        float t = (tid < 8) ? sh[tid] : 0.f;
        t = warpSum(t);
        if (tid == 0) sh[0] = t;
    }
    __syncthreads();
    float mu = sh[0] * (1.0f / DMODEL);
    __syncthreads();
    // variance (two-pass for accuracy)
    float sq = 0.f;
    #pragma unroll
    for (int j = 0; j < 4; j++) { float d = v[j] - mu; sq += d * d; }
    sq = warpSum(sq);
    if ((tid & 31) == 0) sh[tid >> 5] = sq;
    __syncthreads();
    if (tid < 32) {
        float t = (tid < 8) ? sh[tid] : 0.f;
        t = warpSum(t);
        if (tid == 0) sh[0] = t;
    }
    __syncthreads();
    float rstd = rsqrtf(sh[0] * (1.0f / DMODEL) + EPS);
    #pragma unroll
    for (int j = 0; j < 4; j++) {
        int col = tid + 256 * j;
        out[base + col] = (v[j] - mu) * rstd * gamma[col] + beta[col];
    }
}

// ---------------- launch --------------------------------------------------
extern "C" void kernel_launch(void* const* d_in, const int* in_sizes, int n_in,
                              void* d_out, int out_size)
{
    const float* src      = (const float*)d_in[0];   // [B,S,D]
    const float* attnbias = (const float*)d_in[1];   // [H,S,S]
    const float* Wqkv     = (const float*)d_in[2];   // [3D,D]
    const float* bqkv     = (const float*)d_in[3];
    const float* Wo       = (const float*)d_in[4];   // [D,D]
    const float* bo       = (const float*)d_in[5];
    const float* g1       = (const float*)d_in[6];
    const float* b1n      = (const float*)d_in[7];
    const float* g2       = (const float*)d_in[8];
    const float* b2n      = (const float*)d_in[9];
    const float* W1       = (const float*)d_in[10];  // [FF,D]
    const float* b1       = (const float*)d_in[11];
    const float* W2       = (const float*)d_in[12];  // [D,FF]
    const float* b2       = (const float*)d_in[13];
    float* out = (float*)d_out;

    float *qkv, *probs, *ctx, *attnout, *x, *ffh, *ffo;
    cudaGetSymbolAddress((void**)&qkv,     g_qkv);
    cudaGetSymbolAddress((void**)&probs,   g_probs);
    cudaGetSymbolAddress((void**)&ctx,     g_ctx);
    cudaGetSymbolAddress((void**)&attnout, g_attnout);
    cudaGetSymbolAddress((void**)&x,       g_x);
    cudaGetSymbolAddress((void**)&ffh,     g_ffh);
    cudaGetSymbolAddress((void**)&ffo,     g_ffo);

    const long D3 = 3 * DMODEL;   // 3072
    dim3 blk(256);

    // 1) QKV: [4096,1024] @ Wqkv^T -> [4096,3072]  (+bqkv)
    {
        dim3 grid((D3 + BN - 1) / BN, (MS + BM - 1) / BM, 1);
        gemm_kernel<<<grid, blk>>>(src, Wqkv, qkv,
            MS, (int)D3, DMODEL,
            DMODEL, 1, 0, 0,
            DMODEL, 1, 0, 0,
            D3, 0, 0,
            1, bqkv, 0, 0, 1.0f, 0);
    }
    // 2) scores: per (b,h): Q[1024,64] @ K^T -> [1024,1024], *1/8 + attn_bias[h]
    {
        dim3 grid(SEQ / BN, SEQ / BM, BATCH * NHEAD);
        gemm_kernel<<<grid, blk>>>(qkv, qkv + DMODEL, probs,
            SEQ, SEQ, HDIM,
            D3, 1, (long)SEQ * D3, HDIM,
            D3, 1, (long)SEQ * D3, HDIM,
            SEQ, (long)NHEAD * SEQ * SEQ, (long)SEQ * SEQ,
            NHEAD, attnbias, (long)SEQ * SEQ, SEQ, 0.125f, 2);
    }
    // 3) softmax rows
    softmax_kernel<<<BATCH * NHEAD * SEQ, blk>>>(probs);
    // 4) ctx: per (b,h): P[1024,1024] @ V[1024,64] -> ctx[b,:,h*64:(h+1)*64]
    {
        dim3 grid((HDIM + BN - 1) / BN, SEQ / BM, BATCH * NHEAD);
        gemm_kernel<<<grid, blk>>>(probs, qkv + 2 * DMODEL, ctx,
            SEQ, HDIM, SEQ,
            SEQ, 1, (long)NHEAD * SEQ * SEQ, (long)SEQ * SEQ,
            1, D3, (long)SEQ * D3, HDIM,
            DMODEL, (long)SEQ * DMODEL, HDIM,
            NHEAD, nullptr, 0, 0, 1.0f, 3);
    }
    // 5) attn_out = ctx @ Wo^T + bo
    {
        dim3 grid(DMODEL / BN, MS / BM, 1);
        gemm_kernel<<<grid, blk>>>(ctx, Wo, attnout,
            MS, DMODEL, DMODEL,
            DMODEL, 1, 0, 0,
            DMODEL, 1, 0, 0,
            DMODEL, 0, 0,
            1, bo, 0, 0, 1.0f, 0);
    }
    // 6) x = LN(src + attn_out)
    add_ln_kernel<<<MS, blk>>>(src, attnout, g1, b1n, x);
    // 7) ffh = gelu(x @ W1^T + b1)
    {
        dim3 grid(FFDIM / BN, MS / BM, 1);
        gemm_kernel<<<grid, blk>>>(x, W1, ffh,
            MS, FFDIM, DMODEL,
            DMODEL, 1, 0, 0,
            DMODEL, 1, 0, 0,
            FFDIM, 0, 0,
            1, b1, 0, 0, 1.0f, 1);
    }
    // 8) ffo = ffh @ W2^T + b2
    {
        dim3 grid(DMODEL / BN, MS / BM, 1);
        gemm_kernel<<<grid, blk>>>(ffh, W2, ffo,
            MS, DMODEL, FFDIM,
            FFDIM, 1, 0, 0,
            FFDIM, 1, 0, 0,
            DMODEL, 0, 0,
            1, b2, 0, 0, 1.0f, 0);
    }
    // 9) out = LN(x + ffo)
    add_ln_kernel<<<MS, blk>>>(x, ffo, g2, b2n, out);
}

// round 2
// speedup vs baseline: 1.4315x; 1.4315x over previous
#include <cuda_runtime.h>
#include <math.h>

// Problem constants
#define BATCH 4
#define SEQ   1024
#define DMODEL 1024
#define NHEAD 16
#define HDIM  64
#define FFDIM 4096
#define MS    (BATCH*SEQ)        // 4096 rows
#define EPS   1e-5f

// ---------------- scratch (device globals; no allocation allowed) ------------
__device__ float g_qkv[MS * 3 * DMODEL];
__device__ float g_probs[(size_t)BATCH * NHEAD * SEQ * SEQ];
__device__ float g_ctx[MS * DMODEL];
__device__ float g_attnout[MS * DMODEL];
__device__ float g_x[MS * DMODEL];
__device__ float g_ffh[MS * FFDIM];
__device__ float g_ffo[MS * DMODEL];

// ---------------- templated double-buffered SGEMM ---------------------------
// C[z,m,n] = sum_k A[z,m,k] * B[z,n,k]   (+ epilogue)
// AKC: A is k-contiguous (aCS==1, row stride aRS). !AKC: A is m-contiguous (aRS==1).
// Same for BKC with n.
// EPI: 0 = +bias[n]; 1 = gelu(acc+bias[n]); 2 = acc*scale + biasmat[zh,row,col]; 3 = none
// All shapes must divide tiles exactly (true for this problem).
template<int BM,int BN,int BK,int TM,int TN,int EPI,bool AKC,bool BKC>
__global__ void __launch_bounds__(256)
gemm_t(const float* __restrict__ A, const float* __restrict__ B, float* __restrict__ C,
       int K,
       long aRS, long aCS, long aB1, long aB2,
       long bRS, long bCS, long bB1, long bB2,
       long cRS, long cB1, long cB2, int HB,
       const float* __restrict__ bias, long biasB2, long biasRS, float scale)
{
    constexpr int LA = (BM*BK)/(256*4);   // float4 loads per thread for A tile
    constexpr int LB = (BN*BK)/(256*4);

    __shared__ float As[2][BK][BM];
    __shared__ float Bs[2][BK][BN];

    const int tid = threadIdx.x;
    const int m0 = blockIdx.y * BM;
    const int n0 = blockIdx.x * BN;
    const int z  = blockIdx.z;
    const int zb = z / HB, zh = z % HB;

    const float* Az = A + (long)zb*aB1 + (long)zh*aB2;
    const float* Bz = B + (long)zb*bB1 + (long)zh*bB2;
    float*       Cz = C + (long)zb*cB1 + (long)zh*cB2;

    const int tx = tid % (BN/TN);
    const int ty = tid / (BN/TN);

    float acc[TM][TN];
#pragma unroll
    for (int i = 0; i < TM; i++)
#pragma unroll
        for (int j = 0; j < TN; j++) acc[i][j] = 0.f;

    float4 ra[LA], rb[LB];

#define LOAD_AB(k0_) do { \
    for (int i_ = 0; i_ < LA; i_++) { int s_ = tid + 256*i_; \
        if (AKC) { int m_ = s_/(BK/4), kq_ = s_%(BK/4); \
            ra[i_] = *(const float4*)(Az + (long)(m0+m_)*aRS + (k0_) + kq_*4); } \
        else     { int kk_ = s_/(BM/4), mq_ = s_%(BM/4); \
            ra[i_] = *(const float4*)(Az + (long)((k0_)+kk_)*aCS + m0 + mq_*4); } } \
    for (int i_ = 0; i_ < LB; i_++) { int s_ = tid + 256*i_; \
        if (BKC) { int n_ = s_/(BK/4), kq_ = s_%(BK/4); \
            rb[i_] = *(const float4*)(Bz + (long)(n0+n_)*bRS + (k0_) + kq_*4); } \
        else     { int kk_ = s_/(BN/4), nq_ = s_%(BN/4); \
            rb[i_] = *(const float4*)(Bz + (long)((k0_)+kk_)*bCS + n0 + nq_*4); } } \
} while (0)

#define STORE_AB(bw_) do { \
    for (int i_ = 0; i_ < LA; i_++) { int s_ = tid + 256*i_; \
        if (AKC) { int m_ = s_/(BK/4), kq_ = s_%(BK/4); \
            As[bw_][kq_*4+0][m_] = ra[i_].x; As[bw_][kq_*4+1][m_] = ra[i_].y; \
            As[bw_][kq_*4+2][m_] = ra[i_].z; As[bw_][kq_*4+3][m_] = ra[i_].w; } \
        else     { int kk_ = s_/(BM/4), mq_ = s_%(BM/4); \
            *(float4*)&As[bw_][kk_][mq_*4] = ra[i_]; } } \
    for (int i_ = 0; i_ < LB; i_++) { int s_ = tid + 256*i_; \
        if (BKC) { int n_ = s_/(BK/4), kq_ = s_%(BK/4); \
            Bs[bw_][kq_*4+0][n_] = rb[i_].x; Bs[bw_][kq_*4+1][n_] = rb[i_].y; \
            Bs[bw_][kq_*4+2][n_] = rb[i_].z; Bs[bw_][kq_*4+3][n_] = rb[i_].w; } \
        else     { int kk_ = s_/(BN/4), nq_ = s_%(BN/4); \
            *(float4*)&Bs[bw_][kk_][nq_*4] = rb[i_]; } } \
} while (0)

    // prologue: tile 0
    LOAD_AB(0);
    STORE_AB(0);
    __syncthreads();

    const int tiles = K / BK;
    int buf = 0;
    for (int t = 0; t < tiles; t++) {
        if (t + 1 < tiles) LOAD_AB((t + 1) * BK);

        // compute on smem[buf]
#pragma unroll
        for (int kk = 0; kk < BK; kk++) {
            float a[TM], b[TN];
#pragma unroll
            for (int i = 0; i < TM; i += 4) {
                float4 v = *(const float4*)&As[buf][kk][ty*TM + i];
                a[i] = v.x; a[i+1] = v.y; a[i+2] = v.z; a[i+3] = v.w;
            }
#pragma unroll
            for (int j = 0; j < TN; j += 4) {
                float4 v = *(const float4*)&Bs[buf][kk][tx*TN + j];
                b[j] = v.x; b[j+1] = v.y; b[j+2] = v.z; b[j+3] = v.w;
            }
#pragma unroll
            for (int i = 0; i < TM; i++)
#pragma unroll
                for (int j = 0; j < TN; j++)
                    acc[i][j] = fmaf(a[i], b[j], acc[i][j]);
        }

        if (t + 1 < tiles) {
            STORE_AB(buf ^ 1);
            __syncthreads();
        }
        buf ^= 1;
    }
#undef LOAD_AB
#undef STORE_AB

    // epilogue
#pragma unroll
    for (int i = 0; i < TM; i++) {
        long row = m0 + ty*TM + i;
        float* cp = Cz + row*cRS + n0 + tx*TN;
#pragma unroll
        for (int j = 0; j < TN; j++) {
            float v = acc[i][j];
            int col = n0 + tx*TN + j;
            if (EPI == 0) {
                v += bias[col];
            } else if (EPI == 1) {
                v += bias[col];
                v = 0.5f * v * (1.0f + erff(v * 0.70710678118654752f));
            } else if (EPI == 2) {
                v = v * scale + bias[(long)zh*biasB2 + row*biasRS + col];
            }
            cp[j] = v;
        }
    }
}

// ---------------- row softmax over 1024 elements, one block per row ----------
__device__ __forceinline__ float warpMax(float v) {
#pragma unroll
    for (int o = 16; o; o >>= 1) v = fmaxf(v, __shfl_xor_sync(0xffffffffu, v, o));
    return v;
}
__device__ __forceinline__ float warpSum(float v) {
#pragma unroll
    for (int o = 16; o; o >>= 1) v += __shfl_xor_sync(0xffffffffu, v, o);
    return v;
}

__global__ void __launch_bounds__(256) softmax_kernel(float* __restrict__ probs)
{
    float* row = probs + (size_t)blockIdx.x * SEQ;
    const int tid = threadIdx.x;
    __shared__ float sh[8];

    float4 xv = *(const float4*)(row + tid * 4);
    float x[4] = {xv.x, xv.y, xv.z, xv.w};

    float m = fmaxf(fmaxf(x[0], x[1]), fmaxf(x[2], x[3]));
    m = warpMax(m);
    if ((tid & 31) == 0) sh[tid >> 5] = m;
    __syncthreads();
    if (tid < 32) {
        float t = (tid < 8) ? sh[tid] : -INFINITY;
        t = warpMax(t);
        if (tid == 0) sh[0] = t;
    }
    __syncthreads();
    m = sh[0];
    __syncthreads();

    float s = 0.f;
#pragma unroll
    for (int j = 0; j < 4; j++) { x[j] = __expf(x[j] - m); s += x[j]; }
    s = warpSum(s);
    if ((tid & 31) == 0) sh[tid >> 5] = s;
    __syncthreads();
    if (tid < 32) {
        float t = (tid < 8) ? sh[tid] : 0.f;
        t = warpSum(t);
        if (tid == 0) sh[0] = t;
    }
    __syncthreads();
    float inv = 1.0f / sh[0];
    float4 o = make_float4(x[0]*inv, x[1]*inv, x[2]*inv, x[3]*inv);
    *(float4*)(row + tid * 4) = o;
}

// ---------------- residual add + LayerNorm over D=1024, one block per row ----
__global__ void __launch_bounds__(256)
add_ln_kernel(const float* __restrict__ a, const float* __restrict__ b,
              const float* __restrict__ gamma, const float* __restrict__ beta,
              float* __restrict__ out)
{
    const size_t base = (size_t)blockIdx.x * DMODEL;
    const int tid = threadIdx.x;
    __shared__ float sh[8];

    float4 av = *(const float4*)(a + base + tid * 4);
    float4 bv = *(const float4*)(b + base + tid * 4);
    float v[4] = {av.x + bv.x, av.y + bv.y, av.z + bv.z, av.w + bv.w};

    float s = v[0] + v[1] + v[2] + v[3];
    s = warpSum(s);
    if ((tid & 31) == 0) sh[tid >> 5] = s;
    __syncthreads();
    if (tid < 32) {
        float t = (tid < 8) ? sh[tid] : 0.f;
        t = warpSum(t);
        if (tid == 0) sh[0] = t;
    }
    __syncthreads();
    float mu = sh[0] * (1.0f / DMODEL);
    __syncthreads();

    float sq = 0.f;
#pragma unroll
    for (int j = 0; j < 4; j++) { float d = v[j] - mu; sq += d * d; }
    sq = warpSum(sq);
    if ((tid & 31) == 0) sh[tid >> 5] = sq;
    __syncthreads();
    if (tid < 32) {
        float t = (tid < 8) ? sh[tid] : 0.f;
        t = warpSum(t);
        if (tid == 0) sh[0] = t;
    }
    __syncthreads();
    float rstd = rsqrtf(sh[0] * (1.0f / DMODEL) + EPS);

    float4 gv = *(const float4*)(gamma + tid * 4);
    float4 tv = *(const float4*)(beta + tid * 4);
    float4 o;
    o.x = (v[0] - mu) * rstd * gv.x + tv.x;
    o.y = (v[1] - mu) * rstd * gv.y + tv.y;
    o.z = (v[2] - mu) * rstd * gv.z + tv.z;
    o.w = (v[3] - mu) * rstd * gv.w + tv.w;
    *(float4*)(out + base + tid * 4) = o;
}

// ---------------- launch --------------------------------------------------
extern "C" void kernel_launch(void* const* d_in, const int* in_sizes, int n_in,
                              void* d_out, int out_size)
{
    const float* src      = (const float*)d_in[0];   // [B,S,D]
    const float* attnbias = (const float*)d_in[1];   // [H,S,S]
    const float* Wqkv     = (const float*)d_in[2];   // [3D,D]
    const float* bqkv     = (const float*)d_in[3];
    const float* Wo       = (const float*)d_in[4];   // [D,D]
    const float* bo       = (const float*)d_in[5];
    const float* g1       = (const float*)d_in[6];
    const float* b1n      = (const float*)d_in[7];
    const float* g2       = (const float*)d_in[8];
    const float* b2n      = (const float*)d_in[9];
    const float* W1       = (const float*)d_in[10];  // [FF,D]
    const float* b1       = (const float*)d_in[11];
    const float* W2       = (const float*)d_in[12];  // [D,FF]
    const float* b2       = (const float*)d_in[13];
    float* out = (float*)d_out;

    float *qkv, *probs, *ctx, *attnout, *x, *ffh, *ffo;
    cudaGetSymbolAddress((void**)&qkv,     g_qkv);
    cudaGetSymbolAddress((void**)&probs,   g_probs);
    cudaGetSymbolAddress((void**)&ctx,     g_ctx);
    cudaGetSymbolAddress((void**)&attnout, g_attnout);
    cudaGetSymbolAddress((void**)&x,       g_x);
    cudaGetSymbolAddress((void**)&ffh,     g_ffh);
    cudaGetSymbolAddress((void**)&ffo,     g_ffo);

    const long D3 = 3 * DMODEL;   // 3072
    dim3 blk(256);

    // 1) QKV: [4096,1024] @ Wqkv^T -> [4096,3072] (+bqkv)
    {
        dim3 grid(D3 / 128, MS / 128, 1);
        gemm_t<128,128,16,8,8,0,true,true><<<grid, blk>>>(src, Wqkv, qkv,
            DMODEL,
            DMODEL, 1, 0, 0,
            DMODEL, 1, 0, 0,
            D3, 0, 0, 1,
            bqkv, 0, 0, 1.0f);
    }
    // 2) scores: per (b,h): Q[1024,64] @ K^T * 1/8 + attn_bias[h] -> probs
    {
        dim3 grid(SEQ / 128, SEQ / 128, BATCH * NHEAD);
        gemm_t<128,128,16,8,8,2,true,true><<<grid, blk>>>(qkv, qkv + DMODEL, probs,
            HDIM,
            D3, 1, (long)SEQ * D3, HDIM,
            D3, 1, (long)SEQ * D3, HDIM,
            SEQ, (long)NHEAD * SEQ * SEQ, (long)SEQ * SEQ, NHEAD,
            attnbias, (long)SEQ * SEQ, SEQ, 0.125f);
    }
    // 3) softmax rows
    softmax_kernel<<<BATCH * NHEAD * SEQ, blk>>>(probs);
    // 4) ctx: per (b,h): P[1024,1024] @ V[1024,64] -> ctx[b,:,h*64:(h+1)*64]
    {
        dim3 grid(1, SEQ / 128, BATCH * NHEAD);
        gemm_t<128,64,16,8,4,3,true,false><<<grid, blk>>>(probs, qkv + 2 * DMODEL, ctx,
            SEQ,
            SEQ, 1, (long)NHEAD * SEQ * SEQ, (long)SEQ * SEQ,
            1, D3, (long)SEQ * D3, HDIM,
            DMODEL, (long)SEQ * DMODEL, HDIM, NHEAD,
            nullptr, 0, 0, 1.0f);
    }
    // 5) attn_out = ctx @ Wo^T + bo
    {
        dim3 grid(DMODEL / 128, MS / 128, 1);
        gemm_t<128,128,16,8,8,0,true,true><<<grid, blk>>>(ctx, Wo, attnout,
            DMODEL,
            DMODEL, 1, 0, 0,
            DMODEL, 1, 0, 0,
            DMODEL, 0, 0, 1,
            bo, 0, 0, 1.0f);
    }
    // 6) x = LN(src + attn_out)
    add_ln_kernel<<<MS, blk>>>(src, attnout, g1, b1n, x);
    // 7) ffh = gelu(x @ W1^T + b1)
    {
        dim3 grid(FFDIM / 128, MS / 128, 1);
        gemm_t<128,128,16,8,8,1,true,true><<<grid, blk>>>(x, W1, ffh,
            DMODEL,
            DMODEL, 1, 0, 0,
            DMODEL, 1, 0, 0,
            FFDIM, 0, 0, 1,
            b1, 0, 0, 1.0f);
    }
    // 8) ffo = ffh @ W2^T + b2
    {
        dim3 grid(DMODEL / 128, MS / 128, 1);
        gemm_t<128,128,16,8,8,0,true,true><<<grid, blk>>>(ffh, W2, ffo,
            FFDIM,
            FFDIM, 1, 0, 0,
            FFDIM, 1, 0, 0,
            DMODEL, 0, 0, 1,
            b2, 0, 0, 1.0f);
    }
    // 9) out = LN(x + ffo)
    add_ln_kernel<<<MS, blk>>>(x, ffo, g2, b2n, out);
}

// round 4
// speedup vs baseline: 2.5787x; 1.8014x over previous
#include <cuda_runtime.h>
#include <cuda_bf16.h>
#include <math.h>
#include <stdint.h>

// Problem constants
#define BATCH 4
#define SEQ   1024
#define DMODEL 1024
#define NHEAD 16
#define HDIM  64
#define FFDIM 4096
#define MS    (BATCH*SEQ)        // 4096 rows
#define EPS   1e-5f

// ---------------- scratch (device globals; no allocation allowed) ------------
__device__ float g_qkv[MS * 3 * DMODEL];
__device__ float g_probs[(size_t)BATCH * NHEAD * SEQ * SEQ];
__device__ float g_ctx[MS * DMODEL];
__device__ float g_attnout[MS * DMODEL];
__device__ float g_x[MS * DMODEL];
__device__ float g_ffh[MS * FFDIM];
__device__ float g_ffo[MS * DMODEL];

// bf16 split operands (hi/lo)
__device__ __nv_bfloat16 g_srcH[MS * DMODEL],  g_srcL[MS * DMODEL];
__device__ __nv_bfloat16 g_ctxH[MS * DMODEL],  g_ctxL[MS * DMODEL];
__device__ __nv_bfloat16 g_xH[MS * DMODEL],    g_xL[MS * DMODEL];
__device__ __nv_bfloat16 g_ffhH[MS * FFDIM],   g_ffhL[MS * FFDIM];
__device__ __nv_bfloat16 g_WqkvH[3*DMODEL*DMODEL], g_WqkvL[3*DMODEL*DMODEL];
__device__ __nv_bfloat16 g_WoH[DMODEL*DMODEL],     g_WoL[DMODEL*DMODEL];
__device__ __nv_bfloat16 g_W1H[FFDIM*DMODEL],      g_W1L[FFDIM*DMODEL];
__device__ __nv_bfloat16 g_W2H[DMODEL*FFDIM],      g_W2L[DMODEL*FFDIM];

// ================= warp-level bf16 MMA GEMM (sm_80+ mma.sync) ================
// C[m0:128, n0:128] = sum_k A[m,k]*B[n,k], A/B = bf16 hi/lo splits, row-major [.,K]
// acc += Ah*Bh + Ah*Bl + Al*Bh  (3-term split; drops ~2^-18 term)
// EPI: 0 = +bias[n]; 1 = gelu(+bias[n])

#define PITCH 40                 // bf16 elements per smem row (bank-conflict-free frags)
#define TILE  (128*PITCH)        // one operand tile in bf16 elems
#define STG   (4*TILE)           // Ah,Al,Bh,Bl per stage
#define WM_SMEM_BYTES (2*STG*2)  // 2 stages * bf16

__device__ __forceinline__ void mma16816(float* c, const uint32_t* a, const uint32_t* b) {
    asm volatile(
        "mma.sync.aligned.m16n8k16.row.col.f32.bf16.bf16.f32 "
        "{%0,%1,%2,%3}, {%4,%5,%6,%7}, {%8,%9}, {%0,%1,%2,%3};"
        : "+f"(c[0]), "+f"(c[1]), "+f"(c[2]), "+f"(c[3])
        : "r"(a[0]), "r"(a[1]), "r"(a[2]), "r"(a[3]), "r"(b[0]), "r"(b[1]));
}

template<int EPI>
__global__ void __launch_bounds__(256)
gemm_wmma(const __nv_bfloat16* __restrict__ Ah, const __nv_bfloat16* __restrict__ Al,
          const __nv_bfloat16* __restrict__ Bh, const __nv_bfloat16* __restrict__ Bl,
          float* __restrict__ C, int K, int N, const float* __restrict__ bias)
{
    extern __shared__ __nv_bfloat16 sm[];

    const int tid  = threadIdx.x;
    const int wid  = tid >> 5;
    const int lane = tid & 31;
    const int m0 = blockIdx.y * 128;
    const int n0 = blockIdx.x * 128;
    const int wm = wid & 3;        // 4 warps along M (32 rows each)
    const int wn = wid >> 2;       // 2 warps along N (64 cols each)
    const int rr = lane >> 2;      // fragment row/col within 8
    const int kc = (lane & 3) * 2; // fragment k pair

    const __nv_bfloat16* baseAh = Ah + (size_t)m0 * K;
    const __nv_bfloat16* baseAl = Al + (size_t)m0 * K;
    const __nv_bfloat16* baseBh = Bh + (size_t)n0 * K;
    const __nv_bfloat16* baseBl = Bl + (size_t)n0 * K;

    float acc[2][8][4];
#pragma unroll
    for (int i = 0; i < 2; i++)
#pragma unroll
        for (int j = 0; j < 8; j++)
#pragma unroll
            for (int q = 0; q < 4; q++) acc[i][j][q] = 0.f;

    uint4 rg[8];

#define LOADG(kof_) do { \
    _Pragma("unroll") \
    for (int j_ = 0; j_ < 2; j_++) { \
        int q_ = tid + 256*j_; int row_ = q_ >> 2, seg_ = q_ & 3; \
        size_t ga_ = (size_t)row_ * K + (kof_) + seg_ * 8; \
        rg[j_]     = *(const uint4*)(baseAh + ga_); \
        rg[2 + j_] = *(const uint4*)(baseAl + ga_); \
        rg[4 + j_] = *(const uint4*)(baseBh + ga_); \
        rg[6 + j_] = *(const uint4*)(baseBl + ga_); } } while (0)

#define STORES(bw_) do { \
    __nv_bfloat16* sp_ = sm + (bw_) * STG; \
    _Pragma("unroll") \
    for (int j_ = 0; j_ < 2; j_++) { \
        int q_ = tid + 256*j_; int row_ = q_ >> 2, seg_ = q_ & 3; \
        int off_ = row_ * PITCH + seg_ * 8; \
        *(uint4*)(sp_ + off_)            = rg[j_]; \
        *(uint4*)(sp_ + TILE + off_)     = rg[2 + j_]; \
        *(uint4*)(sp_ + 2*TILE + off_)   = rg[4 + j_]; \
        *(uint4*)(sp_ + 3*TILE + off_)   = rg[6 + j_]; } } while (0)

#define SUBSTEP(bw_, k16_) do { \
    const __nv_bfloat16* sAh_ = sm + (bw_) * STG; \
    const __nv_bfloat16* sAl_ = sAh_ + TILE; \
    const __nv_bfloat16* sBh_ = sAh_ + 2*TILE; \
    const __nv_bfloat16* sBl_ = sAh_ + 3*TILE; \
    uint32_t ah_[2][4], al_[2][4], bh_[8][2], bl_[8][2]; \
    _Pragma("unroll") \
    for (int mf_ = 0; mf_ < 2; mf_++) { \
        int ab_ = (wm*32 + mf_*16 + rr) * PITCH + (k16_) + kc; \
        ah_[mf_][0] = *(const uint32_t*)(sAh_ + ab_); \
        ah_[mf_][1] = *(const uint32_t*)(sAh_ + ab_ + 8*PITCH); \
        ah_[mf_][2] = *(const uint32_t*)(sAh_ + ab_ + 8); \
        ah_[mf_][3] = *(const uint32_t*)(sAh_ + ab_ + 8*PITCH + 8); \
        al_[mf_][0] = *(const uint32_t*)(sAl_ + ab_); \
        al_[mf_][1] = *(const uint32_t*)(sAl_ + ab_ + 8*PITCH); \
        al_[mf_][2] = *(const uint32_t*)(sAl_ + ab_ + 8); \
        al_[mf_][3] = *(const uint32_t*)(sAl_ + ab_ + 8*PITCH + 8); } \
    _Pragma("unroll") \
    for (int nf_ = 0; nf_ < 8; nf_++) { \
        int bb_ = (wn*64 + nf_*8 + rr) * PITCH + (k16_) + kc; \
        bh_[nf_][0] = *(const uint32_t*)(sBh_ + bb_); \
        bh_[nf_][1] = *(const uint32_t*)(sBh_ + bb_ + 8); \
        bl_[nf_][0] = *(const uint32_t*)(sBl_ + bb_); \
        bl_[nf_][1] = *(const uint32_t*)(sBl_ + bb_ + 8); } \
    _Pragma("unroll") \
    for (int mf_ = 0; mf_ < 2; mf_++) \
        _Pragma("unroll") \
        for (int nf_ = 0; nf_ < 8; nf_++) { \
            mma16816(acc[mf_][nf_], ah_[mf_], bh_[nf_]); \
            mma16816(acc[mf_][nf_], ah_[mf_], bl_[nf_]); \
            mma16816(acc[mf_][nf_], al_[mf_], bh_[nf_]); } } while (0)

    LOADG(0);
    STORES(0);
    __syncthreads();

    const int tiles = K >> 5;     // BK = 32
    int buf = 0;
    for (int t = 0; t < tiles; t++) {
        if (t + 1 < tiles) LOADG((t + 1) * 32);
        SUBSTEP(buf, 0);
        SUBSTEP(buf, 16);
        if (t + 1 < tiles) {
            STORES(buf ^ 1);
            __syncthreads();
            buf ^= 1;
        }
    }
#undef LOADG
#undef STORES
#undef SUBSTEP

    // epilogue: fragment-direct stores with fused bias/GELU
#pragma unroll
    for (int mf = 0; mf < 2; mf++) {
#pragma unroll
        for (int nf = 0; nf < 8; nf++) {
            const int row = m0 + wm*32 + mf*16 + rr;
            const int col = n0 + wn*64 + nf*8 + kc;
            float b0 = bias[col], b1 = bias[col + 1];
            float v0 = acc[mf][nf][0] + b0;
            float v1 = acc[mf][nf][1] + b1;
            float v2 = acc[mf][nf][2] + b0;
            float v3 = acc[mf][nf][3] + b1;
            if (EPI == 1) {
                v0 = 0.5f * v0 * (1.0f + erff(v0 * 0.70710678118654752f));
                v1 = 0.5f * v1 * (1.0f + erff(v1 * 0.70710678118654752f));
                v2 = 0.5f * v2 * (1.0f + erff(v2 * 0.70710678118654752f));
                v3 = 0.5f * v3 * (1.0f + erff(v3 * 0.70710678118654752f));
            }
            *(float2*)(C + (size_t)row * N + col)       = make_float2(v0, v1);
            *(float2*)(C + (size_t)(row + 8) * N + col) = make_float2(v2, v3);
        }
    }
}

// ================= fp32 -> bf16 hi/lo split ==================================
__global__ void __launch_bounds__(256)
split_kernel(const float* __restrict__ in, __nv_bfloat16* __restrict__ hi,
             __nv_bfloat16* __restrict__ lo)
{
    const size_t i4 = ((size_t)blockIdx.x * 256 + threadIdx.x) * 4;
    float4 v = *(const float4*)(in + i4);
    __nv_bfloat16 h0 = __float2bfloat16_rn(v.x);
    __nv_bfloat16 h1 = __float2bfloat16_rn(v.y);
    __nv_bfloat16 h2 = __float2bfloat16_rn(v.z);
    __nv_bfloat16 h3 = __float2bfloat16_rn(v.w);
    __nv_bfloat162 H01; H01.x = h0; H01.y = h1;
    __nv_bfloat162 H23; H23.x = h2; H23.y = h3;
    *(__nv_bfloat162*)(hi + i4)     = H01;
    *(__nv_bfloat162*)(hi + i4 + 2) = H23;
    __nv_bfloat162 L01, L23;
    L01.x = __float2bfloat16_rn(v.x - __bfloat162float(h0));
    L01.y = __float2bfloat16_rn(v.y - __bfloat162float(h1));
    L23.x = __float2bfloat16_rn(v.z - __bfloat162float(h2));
    L23.y = __float2bfloat16_rn(v.w - __bfloat162float(h3));
    *(__nv_bfloat162*)(lo + i4)     = L01;
    *(__nv_bfloat162*)(lo + i4 + 2) = L23;
}

// ================= SIMT SGEMM (attention path) ===============================
template<int BM,int BN,int BK,int TM,int TN,int EPI,bool AKC,bool BKC>
__global__ void __launch_bounds__(256)
gemm_t(const float* __restrict__ A, const float* __restrict__ B, float* __restrict__ C,
       int K,
       long aRS, long aCS, long aB1, long aB2,
       long bRS, long bCS, long bB1, long bB2,
       long cRS, long cB1, long cB2, int HB,
       const float* __restrict__ bias, long biasB2, long biasRS, float scale)
{
    constexpr int LA = (BM*BK)/(256*4);
    constexpr int LB = (BN*BK)/(256*4);

    __shared__ float As[2][BK][BM];
    __shared__ float Bs[2][BK][BN];

    const int tid = threadIdx.x;
    const int m0 = blockIdx.y * BM;
    const int n0 = blockIdx.x * BN;
    const int z  = blockIdx.z;
    const int zb = z / HB, zh = z % HB;

    const float* Az = A + (long)zb*aB1 + (long)zh*aB2;
    const float* Bz = B + (long)zb*bB1 + (long)zh*bB2;
    float*       Cz = C + (long)zb*cB1 + (long)zh*cB2;

    const int tx = tid % (BN/TN);
    const int ty = tid / (BN/TN);

    float acc[TM][TN];
#pragma unroll
    for (int i = 0; i < TM; i++)
#pragma unroll
        for (int j = 0; j < TN; j++) acc[i][j] = 0.f;

    float4 ra[LA], rb[LB];

#define LOAD_AB(k0_) do { \
    for (int i_ = 0; i_ < LA; i_++) { int s_ = tid + 256*i_; \
        if (AKC) { int m_ = s_/(BK/4), kq_ = s_%(BK/4); \
            ra[i_] = *(const float4*)(Az + (long)(m0+m_)*aRS + (k0_) + kq_*4); } \
        else     { int kk_ = s_/(BM/4), mq_ = s_%(BM/4); \
            ra[i_] = *(const float4*)(Az + (long)((k0_)+kk_)*aCS + m0 + mq_*4); } } \
    for (int i_ = 0; i_ < LB; i_++) { int s_ = tid + 256*i_; \
        if (BKC) { int n_ = s_/(BK/4), kq_ = s_%(BK/4); \
            rb[i_] = *(const float4*)(Bz + (long)(n0+n_)*bRS + (k0_) + kq_*4); } \
        else     { int kk_ = s_/(BN/4), nq_ = s_%(BN/4); \
            rb[i_] = *(const float4*)(Bz + (long)((k0_)+kk_)*bCS + n0 + nq_*4); } } \
} while (0)

#define STORE_AB(bw_) do { \
    for (int i_ = 0; i_ < LA; i_++) { int s_ = tid + 256*i_; \
        if (AKC) { int m_ = s_/(BK/4), kq_ = s_%(BK/4); \
            As[bw_][kq_*4+0][m_] = ra[i_].x; As[bw_][kq_*4+1][m_] = ra[i_].y; \
            As[bw_][kq_*4+2][m_] = ra[i_].z; As[bw_][kq_*4+3][m_] = ra[i_].w; } \
        else     { int kk_ = s_/(BM/4), mq_ = s_%(BM/4); \
            *(float4*)&As[bw_][kk_][mq_*4] = ra[i_]; } } \
    for (int i_ = 0; i_ < LB; i_++) { int s_ = tid + 256*i_; \
        if (BKC) { int n_ = s_/(BK/4), kq_ = s_%(BK/4); \
            Bs[bw_][kq_*4+0][n_] = rb[i_].x; Bs[bw_][kq_*4+1][n_] = rb[i_].y; \
            Bs[bw_][kq_*4+2][n_] = rb[i_].z; Bs[bw_][kq_*4+3][n_] = rb[i_].w; } \
        else     { int kk_ = s_/(BN/4), nq_ = s_%(BN/4); \
            *(float4*)&Bs[bw_][kk_][nq_*4] = rb[i_]; } } \
} while (0)

    LOAD_AB(0);
    STORE_AB(0);
    __syncthreads();

    const int tiles = K / BK;
    int buf = 0;
    for (int t = 0; t < tiles; t++) {
        if (t + 1 < tiles) LOAD_AB((t + 1) * BK);

#pragma unroll
        for (int kk = 0; kk < BK; kk++) {
            float a[TM], b[TN];
#pragma unroll
            for (int i = 0; i < TM; i += 4) {
                float4 v = *(const float4*)&As[buf][kk][ty*TM + i];
                a[i] = v.x; a[i+1] = v.y; a[i+2] = v.z; a[i+3] = v.w;
            }
#pragma unroll
            for (int j = 0; j < TN; j += 4) {
                float4 v = *(const float4*)&Bs[buf][kk][tx*TN + j];
                b[j] = v.x; b[j+1] = v.y; b[j+2] = v.z; b[j+3] = v.w;
            }
#pragma unroll
            for (int i = 0; i < TM; i++)
#pragma unroll
                for (int j = 0; j < TN; j++)
                    acc[i][j] = fmaf(a[i], b[j], acc[i][j]);
        }

        if (t + 1 < tiles) {
            STORE_AB(buf ^ 1);
            __syncthreads();
        }
        buf ^= 1;
    }
#undef LOAD_AB
#undef STORE_AB

#pragma unroll
    for (int i = 0; i < TM; i++) {
        long row = m0 + ty*TM + i;
        float* cp = Cz + row*cRS + n0 + tx*TN;
#pragma unroll
        for (int j = 0; j < TN; j++) {
            float v = acc[i][j];
            int col = n0 + tx*TN + j;
            if (EPI == 0) {
                v += bias[col];
            } else if (EPI == 1) {
                v += bias[col];
                v = 0.5f * v * (1.0f + erff(v * 0.70710678118654752f));
            } else if (EPI == 2) {
                v = v * scale + bias[(long)zh*biasB2 + row*biasRS + col];
            }
            cp[j] = v;
        }
    }
}

// ---------------- row softmax over 1024 elements -----------------------------
__device__ __forceinline__ float warpMax(float v) {
#pragma unroll
    for (int o = 16; o; o >>= 1) v = fmaxf(v, __shfl_xor_sync(0xffffffffu, v, o));
    return v;
}
__device__ __forceinline__ float warpSum(float v) {
#pragma unroll
    for (int o = 16; o; o >>= 1) v += __shfl_xor_sync(0xffffffffu, v, o);
    return v;
}

__global__ void __launch_bounds__(256) softmax_kernel(float* __restrict__ probs)
{
    float* row = probs + (size_t)blockIdx.x * SEQ;
    const int tid = threadIdx.x;
    __shared__ float sh[8];

    float4 xv = *(const float4*)(row + tid * 4);
    float x[4] = {xv.x, xv.y, xv.z, xv.w};

    float m = fmaxf(fmaxf(x[0], x[1]), fmaxf(x[2], x[3]));
    m = warpMax(m);
    if ((tid & 31) == 0) sh[tid >> 5] = m;
    __syncthreads();
    if (tid < 32) {
        float t = (tid < 8) ? sh[tid] : -INFINITY;
        t = warpMax(t);
        if (tid == 0) sh[0] = t;
    }
    __syncthreads();
    m = sh[0];
    __syncthreads();

    float s = 0.f;
#pragma unroll
    for (int j = 0; j < 4; j++) { x[j] = __expf(x[j] - m); s += x[j]; }
    s = warpSum(s);
    if ((tid & 31) == 0) sh[tid >> 5] = s;
    __syncthreads();
    if (tid < 32) {
        float t = (tid < 8) ? sh[tid] : 0.f;
        t = warpSum(t);
        if (tid == 0) sh[0] = t;
    }
    __syncthreads();
    float inv = 1.0f / sh[0];
    float4 o = make_float4(x[0]*inv, x[1]*inv, x[2]*inv, x[3]*inv);
    *(float4*)(row + tid * 4) = o;
}

// ---------------- residual add + LayerNorm -----------------------------------
__global__ void __launch_bounds__(256)
add_ln_kernel(const float* __restrict__ a, const float* __restrict__ b,
              const float* __restrict__ gamma, const float* __restrict__ beta,
              float* __restrict__ out)
{
    const size_t base = (size_t)blockIdx.x * DMODEL;
    const int tid = threadIdx.x;
    __shared__ float sh[8];

    float4 av = *(const float4*)(a + base + tid * 4);
    float4 bv = *(const float4*)(b + base + tid * 4);
    float v[4] = {av.x + bv.x, av.y + bv.y, av.z + bv.z, av.w + bv.w};

    float s = v[0] + v[1] + v[2] + v[3];
    s = warpSum(s);
    if ((tid & 31) == 0) sh[tid >> 5] = s;
    __syncthreads();
    if (tid < 32) {
        float t = (tid < 8) ? sh[tid] : 0.f;
        t = warpSum(t);
        if (tid == 0) sh[0] = t;
    }
    __syncthreads();
    float mu = sh[0] * (1.0f / DMODEL);
    __syncthreads();

    float sq = 0.f;
#pragma unroll
    for (int j = 0; j < 4; j++) { float d = v[j] - mu; sq += d * d; }
    sq = warpSum(sq);
    if ((tid & 31) == 0) sh[tid >> 5] = sq;
    __syncthreads();
    if (tid < 32) {
        float t = (tid < 8) ? sh[tid] : 0.f;
        t = warpSum(t);
        if (tid == 0) sh[0] = t;
    }
    __syncthreads();
    float rstd = rsqrtf(sh[0] * (1.0f / DMODEL) + EPS);

    float4 gv = *(const float4*)(gamma + tid * 4);
    float4 tv = *(const float4*)(beta + tid * 4);
    float4 o;
    o.x = (v[0] - mu) * rstd * gv.x + tv.x;
    o.y = (v[1] - mu) * rstd * gv.y + tv.y;
    o.z = (v[2] - mu) * rstd * gv.z + tv.z;
    o.w = (v[3] - mu) * rstd * gv.w + tv.w;
    *(float4*)(out + base + tid * 4) = o;
}

// ---------------- launch ------------------------------------------------------
extern "C" void kernel_launch(void* const* d_in, const int* in_sizes, int n_in,
                              void* d_out, int out_size)
{
    const float* src      = (const float*)d_in[0];
    const float* attnbias = (const float*)d_in[1];
    const float* Wqkv     = (const float*)d_in[2];
    const float* bqkv     = (const float*)d_in[3];
    const float* Wo       = (const float*)d_in[4];
    const float* bo       = (const float*)d_in[5];
    const float* g1       = (const float*)d_in[6];
    const float* b1n      = (const float*)d_in[7];
    const float* g2       = (const float*)d_in[8];
    const float* b2n      = (const float*)d_in[9];
    const float* W1       = (const float*)d_in[10];
    const float* b1       = (const float*)d_in[11];
    const float* W2       = (const float*)d_in[12];
    const float* b2       = (const float*)d_in[13];
    float* out = (float*)d_out;

    float *qkv, *probs, *ctx, *attnout, *x, *ffh, *ffo;
    cudaGetSymbolAddress((void**)&qkv,     g_qkv);
    cudaGetSymbolAddress((void**)&probs,   g_probs);
    cudaGetSymbolAddress((void**)&ctx,     g_ctx);
    cudaGetSymbolAddress((void**)&attnout, g_attnout);
    cudaGetSymbolAddress((void**)&x,       g_x);
    cudaGetSymbolAddress((void**)&ffh,     g_ffh);
    cudaGetSymbolAddress((void**)&ffo,     g_ffo);

    __nv_bfloat16 *srcH,*srcL,*ctxH,*ctxL,*xH,*xL,*ffhH,*ffhL;
    __nv_bfloat16 *WqkvH,*WqkvL,*WoH,*WoL,*W1H,*W1L,*W2H,*W2L;
    cudaGetSymbolAddress((void**)&srcH, g_srcH);   cudaGetSymbolAddress((void**)&srcL, g_srcL);
    cudaGetSymbolAddress((void**)&ctxH, g_ctxH);   cudaGetSymbolAddress((void**)&ctxL, g_ctxL);
    cudaGetSymbolAddress((void**)&xH,   g_xH);     cudaGetSymbolAddress((void**)&xL,   g_xL);
    cudaGetSymbolAddress((void**)&ffhH, g_ffhH);   cudaGetSymbolAddress((void**)&ffhL, g_ffhL);
    cudaGetSymbolAddress((void**)&WqkvH,g_WqkvH);  cudaGetSymbolAddress((void**)&WqkvL,g_WqkvL);
    cudaGetSymbolAddress((void**)&WoH,  g_WoH);    cudaGetSymbolAddress((void**)&WoL,  g_WoL);
    cudaGetSymbolAddress((void**)&W1H,  g_W1H);    cudaGetSymbolAddress((void**)&W1L,  g_W1L);
    cudaGetSymbolAddress((void**)&W2H,  g_W2H);    cudaGetSymbolAddress((void**)&W2L,  g_W2L);

    cudaFuncSetAttribute(gemm_wmma<0>, cudaFuncAttributeMaxDynamicSharedMemorySize, WM_SMEM_BYTES);
    cudaFuncSetAttribute(gemm_wmma<1>, cudaFuncAttributeMaxDynamicSharedMemorySize, WM_SMEM_BYTES);

    const long D3 = 3 * DMODEL;
    dim3 blk(256);

    // splits for dense GEMM operands
    split_kernel<<<MS*DMODEL/1024, blk>>>(src,  srcH, srcL);
    split_kernel<<<3*DMODEL*DMODEL/1024, blk>>>(Wqkv, WqkvH, WqkvL);
    split_kernel<<<DMODEL*DMODEL/1024, blk>>>(Wo,   WoH,   WoL);
    split_kernel<<<FFDIM*DMODEL/1024, blk>>>(W1,   W1H,   W1L);
    split_kernel<<<DMODEL*FFDIM/1024, blk>>>(W2,   W2H,   W2L);

    // 1) QKV = src @ Wqkv^T + bqkv   [4096,3072]
    gemm_wmma<0><<<dim3(3*DMODEL/128, MS/128), blk, WM_SMEM_BYTES>>>(
        srcH, srcL, WqkvH, WqkvL, qkv, DMODEL, 3*DMODEL, bqkv);

    // 2) scores (SIMT): per (b,h): Q @ K^T * 1/8 + attn_bias[h]
    {
        dim3 grid(SEQ / 128, SEQ / 128, BATCH * NHEAD);
        gemm_t<128,128,16,8,8,2,true,true><<<grid, blk>>>(qkv, qkv + DMODEL, probs,
            HDIM,
            D3, 1, (long)SEQ * D3, HDIM,
            D3, 1, (long)SEQ * D3, HDIM,
            SEQ, (long)NHEAD * SEQ * SEQ, (long)SEQ * SEQ, NHEAD,
            attnbias, (long)SEQ * SEQ, SEQ, 0.125f);
    }
    // 3) softmax
    softmax_kernel<<<BATCH * NHEAD * SEQ, blk>>>(probs);
    // 4) ctx (SIMT): P @ V
    {
        dim3 grid(1, SEQ / 128, BATCH * NHEAD);
        gemm_t<128,64,16,8,4,3,true,false><<<grid, blk>>>(probs, qkv + 2 * DMODEL, ctx,
            SEQ,
            SEQ, 1, (long)NHEAD * SEQ * SEQ, (long)SEQ * SEQ,
            1, D3, (long)SEQ * D3, HDIM,
            DMODEL, (long)SEQ * DMODEL, HDIM, NHEAD,
            nullptr, 0, 0, 1.0f);
    }
    // 5) attn_out = ctx @ Wo^T + bo
    split_kernel<<<MS*DMODEL/1024, blk>>>(ctx, ctxH, ctxL);
    gemm_wmma<0><<<dim3(DMODEL/128, MS/128), blk, WM_SMEM_BYTES>>>(
        ctxH, ctxL, WoH, WoL, attnout, DMODEL, DMODEL, bo);

    // 6) x = LN(src + attn_out)
    add_ln_kernel<<<MS, blk>>>(src, attnout, g1, b1n, x);

    // 7) ffh = gelu(x @ W1^T + b1)
    split_kernel<<<MS*DMODEL/1024, blk>>>(x, xH, xL);
    gemm_wmma<1><<<dim3(FFDIM/128, MS/128), blk, WM_SMEM_BYTES>>>(
        xH, xL, W1H, W1L, ffh, DMODEL, FFDIM, b1);

    // 8) ffo = ffh @ W2^T + b2
    split_kernel<<<MS*FFDIM/1024, blk>>>(ffh, ffhH, ffhL);
    gemm_wmma<0><<<dim3(DMODEL/128, MS/128), blk, WM_SMEM_BYTES>>>(
        ffhH, ffhL, W2H, W2L, ffo, FFDIM, DMODEL, b2);

    // 9) out = LN(x + ffo)
    add_ln_kernel<<<MS, blk>>>(x, ffo, g2, b2n, out);
}

// round 5
// speedup vs baseline: 3.8092x; 1.4772x over previous
#include <cuda_runtime.h>
#include <cuda_bf16.h>
#include <math.h>
#include <stdint.h>

// Problem constants
#define BATCH 4
#define SEQ   1024
#define DMODEL 1024
#define NHEAD 16
#define HDIM  64
#define FFDIM 4096
#define MS    (BATCH*SEQ)
#define EPS   1e-5f

// ---------------- scratch (device globals) -----------------------------------
__device__ float g_probs[(size_t)BATCH * NHEAD * SEQ * SEQ];
__device__ float g_attnout[MS * DMODEL];
__device__ float g_x[MS * DMODEL];
__device__ float g_ffo[MS * DMODEL];

__device__ __nv_bfloat16 g_srcH[MS * DMODEL],  g_srcL[MS * DMODEL];
__device__ __nv_bfloat16 g_qkvH[MS * 3 * DMODEL], g_qkvL[MS * 3 * DMODEL];
__device__ __nv_bfloat16 g_phH[(size_t)BATCH * NHEAD * SEQ * SEQ];
__device__ __nv_bfloat16 g_phL[(size_t)BATCH * NHEAD * SEQ * SEQ];
__device__ __nv_bfloat16 g_ctxH[MS * DMODEL],  g_ctxL[MS * DMODEL];
__device__ __nv_bfloat16 g_xH[MS * DMODEL],    g_xL[MS * DMODEL];
__device__ __nv_bfloat16 g_ffhH[MS * FFDIM],   g_ffhL[MS * FFDIM];
__device__ __nv_bfloat16 g_WqkvH[3*DMODEL*DMODEL], g_WqkvL[3*DMODEL*DMODEL];
__device__ __nv_bfloat16 g_WoH[DMODEL*DMODEL],     g_WoL[DMODEL*DMODEL];
__device__ __nv_bfloat16 g_W1H[FFDIM*DMODEL],      g_W1L[FFDIM*DMODEL];
__device__ __nv_bfloat16 g_W2H[DMODEL*FFDIM],      g_W2L[DMODEL*FFDIM];

// ================= MMA helpers ================================================
__device__ __forceinline__ void mma16816(float* c, const uint32_t* a,
                                         uint32_t b0, uint32_t b1) {
    asm volatile(
        "mma.sync.aligned.m16n8k16.row.col.f32.bf16.bf16.f32 "
        "{%0,%1,%2,%3}, {%4,%5,%6,%7}, {%8,%9}, {%0,%1,%2,%3};"
        : "+f"(c[0]), "+f"(c[1]), "+f"(c[2]), "+f"(c[3])
        : "r"(a[0]), "r"(a[1]), "r"(a[2]), "r"(a[3]), "r"(b0), "r"(b1));
}
__device__ __forceinline__ void ldsm_x4(uint32_t* r, uint32_t addr) {
    asm volatile("ldmatrix.sync.aligned.m8n8.x4.shared.b16 {%0,%1,%2,%3}, [%4];"
        : "=r"(r[0]), "=r"(r[1]), "=r"(r[2]), "=r"(r[3]) : "r"(addr));
}
__device__ __forceinline__ void ldsm_x4t(uint32_t* r, uint32_t addr) {
    asm volatile("ldmatrix.sync.aligned.m8n8.x4.trans.shared.b16 {%0,%1,%2,%3}, [%4];"
        : "=r"(r[0]), "=r"(r[1]), "=r"(r[2]), "=r"(r[3]) : "r"(addr));
}

#define PITCH 40                       // bf16 elems per smem row
#define TILE_E (128*PITCH)             // elems per operand tile
#define TILE_B (TILE_E*2)              // 10240 bytes
#define STG_B  (4*TILE_B)              // 40960 bytes per stage
#define DSMEM  (2*STG_B)               // 81920

// ================= dense / scores bf16-split MMA GEMM ========================
// C[z, m0:128, n0:128] = sum_k A[m,k]*B[n,k] ; A,B bf16 hi/lo, k-contiguous rows
// EPI: 0 +bias -> f32 C ; 2 *scale + biasmat -> f32 C ;
//      4 +bias -> split (Ch,Cl) ; 5 gelu(+bias) -> split (Ch,Cl)
template<int EPI>
__global__ void __launch_bounds__(256)
gemm_bf16s(const __nv_bfloat16* __restrict__ Ah, const __nv_bfloat16* __restrict__ Al,
           const __nv_bfloat16* __restrict__ Bh, const __nv_bfloat16* __restrict__ Bl,
           float* __restrict__ C, __nv_bfloat16* __restrict__ Ch, __nv_bfloat16* __restrict__ Cl,
           int K, int cRS,
           long aRS, long aB1, long aB2,
           long bRS, long bB1, long bB2,
           long cB1, long cB2, int HB,
           const float* __restrict__ bias, long biasB2, long biasRS, float scale)
{
    extern __shared__ char smc[];
    __nv_bfloat16* sm = (__nv_bfloat16*)smc;
    const uint32_t sbase = (uint32_t)__cvta_generic_to_shared(smc);

    const int tid = threadIdx.x, wid = tid >> 5, lane = tid & 31;
    const int m0 = blockIdx.y * 128, n0 = blockIdx.x * 128;
    const int z = blockIdx.z, zb = z / HB, zh = z % HB;
    const int wm = wid & 3, wn = wid >> 2;
    const int rr = lane >> 2, kc = (lane & 3) * 2;

    const __nv_bfloat16* pAh = Ah + zb*aB1 + zh*aB2 + (size_t)m0*aRS;
    const __nv_bfloat16* pAl = Al + zb*aB1 + zh*aB2 + (size_t)m0*aRS;
    const __nv_bfloat16* pBh = Bh + zb*bB1 + zh*bB2 + (size_t)n0*bRS;
    const __nv_bfloat16* pBl = Bl + zb*bB1 + zh*bB2 + (size_t)n0*bRS;

    float acc[2][8][4];
#pragma unroll
    for (int i=0;i<2;i++)
#pragma unroll
        for (int j=0;j<8;j++)
#pragma unroll
            for (int q=0;q<4;q++) acc[i][j][q]=0.f;

    uint4 rg[8];
    const int lrow = tid >> 2, lseg = tid & 3;

#define LOADG(kof_) do { \
    _Pragma("unroll") \
    for (int j_=0;j_<2;j_++){ int row_=lrow+64*j_; \
        size_t ga_=(size_t)row_*aRS+(kof_)+lseg*8; \
        size_t gb_=(size_t)row_*bRS+(kof_)+lseg*8; \
        rg[j_]   = *(const uint4*)(pAh+ga_); rg[2+j_]=*(const uint4*)(pAl+ga_); \
        rg[4+j_] = *(const uint4*)(pBh+gb_); rg[6+j_]=*(const uint4*)(pBl+gb_);} } while(0)

#define STORES(bw_) do { \
    __nv_bfloat16* sp_ = sm + (bw_)*(STG_B/2); \
    _Pragma("unroll") \
    for (int j_=0;j_<2;j_++){ int row_=lrow+64*j_; int off_=row_*PITCH+lseg*8; \
        *(uint4*)(sp_+off_)=rg[j_];            *(uint4*)(sp_+TILE_E+off_)=rg[2+j_]; \
        *(uint4*)(sp_+2*TILE_E+off_)=rg[4+j_]; *(uint4*)(sp_+3*TILE_E+off_)=rg[6+j_];} } while(0)

    const uint32_t aoff = (uint32_t)((lane & 15)*80 + (lane & 16));
    const uint32_t boff = (uint32_t)((((lane & 16) >> 1) + (lane & 7))*80 + ((lane & 8) ? 16 : 0));

#define SUBSTEP(bw_, k16_) do { \
    const uint32_t sA_ = sbase + (bw_)*STG_B; \
    uint32_t ah_[2][4], al_[2][4], bh_[4][4], bl_[4][4]; \
    uint32_t aB_ = sA_ + aoff + (k16_)*2 + wm*32*80; \
    ldsm_x4(ah_[0], aB_);          ldsm_x4(ah_[1], aB_ + 16*80); \
    ldsm_x4(al_[0], aB_ + TILE_B); ldsm_x4(al_[1], aB_ + TILE_B + 16*80); \
    uint32_t bB_ = sA_ + 2*TILE_B + boff + (k16_)*2 + wn*64*80; \
    _Pragma("unroll") \
    for (int n2_=0;n2_<4;n2_++){ ldsm_x4(bh_[n2_], bB_ + n2_*16*80); \
                                 ldsm_x4(bl_[n2_], bB_ + TILE_B + n2_*16*80);} \
    _Pragma("unroll") \
    for (int mf_=0;mf_<2;mf_++) \
        _Pragma("unroll") \
        for (int nf_=0;nf_<8;nf_++){ \
            uint32_t b0_=bh_[nf_>>1][(nf_&1)*2], b1_=bh_[nf_>>1][(nf_&1)*2+1]; \
            uint32_t c0_=bl_[nf_>>1][(nf_&1)*2], c1_=bl_[nf_>>1][(nf_&1)*2+1]; \
            mma16816(acc[mf_][nf_], ah_[mf_], b0_, b1_); \
            mma16816(acc[mf_][nf_], ah_[mf_], c0_, c1_); \
            mma16816(acc[mf_][nf_], al_[mf_], b0_, b1_);} } while(0)

    LOADG(0);
    STORES(0);
    __syncthreads();

    const int tiles = K >> 5;
    int buf = 0;
    for (int t = 0; t < tiles; t++) {
        if (t + 1 < tiles) LOADG((t + 1) * 32);
        SUBSTEP(buf, 0);
        SUBSTEP(buf, 16);
        if (t + 1 < tiles) {
            STORES(buf ^ 1);
            __syncthreads();
            buf ^= 1;
        }
    }
#undef LOADG
#undef STORES
#undef SUBSTEP

    float* Cz = (EPI <= 2) ? C + zb*cB1 + zh*cB2 : nullptr;
    __nv_bfloat16* Chz = (EPI >= 4) ? Ch + zb*cB1 + zh*cB2 : nullptr;
    __nv_bfloat16* Clz = (EPI >= 4) ? Cl + zb*cB1 + zh*cB2 : nullptr;

#pragma unroll
    for (int mf = 0; mf < 2; mf++) {
#pragma unroll
        for (int nf = 0; nf < 8; nf++) {
            const int row = m0 + wm*32 + mf*16 + rr;
            const int col = n0 + wn*64 + nf*8 + kc;
            float v0 = acc[mf][nf][0], v1 = acc[mf][nf][1];
            float v2 = acc[mf][nf][2], v3 = acc[mf][nf][3];
            if (EPI == 0 || EPI == 4 || EPI == 5) {
                float b0 = bias[col], b1 = bias[col+1];
                v0 += b0; v1 += b1; v2 += b0; v3 += b1;
            }
            if (EPI == 5) {
                v0 = 0.5f*v0*(1.0f+erff(v0*0.70710678118654752f));
                v1 = 0.5f*v1*(1.0f+erff(v1*0.70710678118654752f));
                v2 = 0.5f*v2*(1.0f+erff(v2*0.70710678118654752f));
                v3 = 0.5f*v3*(1.0f+erff(v3*0.70710678118654752f));
            }
            if (EPI == 2) {
                const float* bm = bias + zh*biasB2 + (size_t)row*biasRS + col;
                float2 q0 = *(const float2*)bm;
                float2 q1 = *(const float2*)(bm + 8*biasRS);
                v0 = v0*scale + q0.x; v1 = v1*scale + q0.y;
                v2 = v2*scale + q1.x; v3 = v3*scale + q1.y;
            }
            if (EPI <= 2) {
                *(float2*)(Cz + (size_t)row*cRS + col)     = make_float2(v0, v1);
                *(float2*)(Cz + (size_t)(row+8)*cRS + col) = make_float2(v2, v3);
            } else {
                __nv_bfloat162 h01, h23, l01, l23;
                h01.x = __float2bfloat16_rn(v0); h01.y = __float2bfloat16_rn(v1);
                h23.x = __float2bfloat16_rn(v2); h23.y = __float2bfloat16_rn(v3);
                l01.x = __float2bfloat16_rn(v0 - __bfloat162float(h01.x));
                l01.y = __float2bfloat16_rn(v1 - __bfloat162float(h01.y));
                l23.x = __float2bfloat16_rn(v2 - __bfloat162float(h23.x));
                l23.y = __float2bfloat16_rn(v3 - __bfloat162float(h23.y));
                *(__nv_bfloat162*)(Chz + (size_t)row*cRS + col)     = h01;
                *(__nv_bfloat162*)(Chz + (size_t)(row+8)*cRS + col) = h23;
                *(__nv_bfloat162*)(Clz + (size_t)row*cRS + col)     = l01;
                *(__nv_bfloat162*)(Clz + (size_t)(row+8)*cRS + col) = l23;
            }
        }
    }
}

// ================= ctx MMA: P[t,s] @ V[s,d] with V via ldmatrix.trans ========
// per z=(b,h): C[128 t, 64 d] tiles; K=1024. Output split bf16 (ctxH/ctxL).
#define VPITCH 72
#define CA_B   (128*PITCH*2)          // 10240
#define CB_B   (32*VPITCH*2)          // 4608
#define CSTG_B (2*CA_B + 2*CB_B)      // 29696
#define CSMEM  (2*CSTG_B)             // 59392

__global__ void __launch_bounds__(256)
ctx_bf16s(const __nv_bfloat16* __restrict__ Ph, const __nv_bfloat16* __restrict__ Pl,
          const __nv_bfloat16* __restrict__ Vh, const __nv_bfloat16* __restrict__ Vl,
          __nv_bfloat16* __restrict__ Ch, __nv_bfloat16* __restrict__ Cl)
{
    extern __shared__ char smc[];
    __nv_bfloat16* sm = (__nv_bfloat16*)smc;
    const uint32_t sbase = (uint32_t)__cvta_generic_to_shared(smc);

    const int tid = threadIdx.x, wid = tid >> 5, lane = tid & 31;
    const int m0 = blockIdx.y * 128;
    const int z = blockIdx.z, zb = z >> 4, zh = z & 15;
    const int wm = wid & 3, wn = wid >> 2;
    const int rr = lane >> 2, kc = (lane & 3) * 2;

    const __nv_bfloat16* pAh = Ph + (size_t)z * SEQ * SEQ + (size_t)m0 * SEQ;
    const __nv_bfloat16* pAl = Pl + (size_t)z * SEQ * SEQ + (size_t)m0 * SEQ;
    const __nv_bfloat16* pBh = Vh + (size_t)zb * SEQ * 3072 + zh * 64;
    const __nv_bfloat16* pBl = Vl + (size_t)zb * SEQ * 3072 + zh * 64;

    float acc[2][4][4];
#pragma unroll
    for (int i=0;i<2;i++)
#pragma unroll
        for (int j=0;j<4;j++)
#pragma unroll
            for (int q=0;q<4;q++) acc[i][j][q]=0.f;

    uint4 rg[6];
    const int lrow = tid >> 2, lseg = tid & 3;       // A loader
    const int vrow = tid >> 3, vseg = tid & 7;       // B loader (32 x 64)

#define LOADG(kof_) do { \
    _Pragma("unroll") \
    for (int j_=0;j_<2;j_++){ int row_=lrow+64*j_; \
        size_t ga_=(size_t)row_*SEQ+(kof_)+lseg*8; \
        rg[j_]=*(const uint4*)(pAh+ga_); rg[2+j_]=*(const uint4*)(pAl+ga_);} \
    { size_t gb_=(size_t)((kof_)+vrow)*3072+vseg*8; \
      rg[4]=*(const uint4*)(pBh+gb_); rg[5]=*(const uint4*)(pBl+gb_);} } while(0)

#define STORES(bw_) do { \
    __nv_bfloat16* sp_ = sm + (bw_)*(CSTG_B/2); \
    _Pragma("unroll") \
    for (int j_=0;j_<2;j_++){ int row_=lrow+64*j_; int off_=row_*PITCH+lseg*8; \
        *(uint4*)(sp_+off_)=rg[j_]; *(uint4*)(sp_+TILE_E+off_)=rg[2+j_];} \
    { int off_=vrow*VPITCH+vseg*8; \
      *(uint4*)(sp_+2*TILE_E+off_)=rg[4]; \
      *(uint4*)(sp_+2*TILE_E+32*VPITCH+off_)=rg[5];} } while(0)

    const uint32_t aoff = (uint32_t)((lane & 15)*80 + (lane & 16));
    const uint32_t voff = (uint32_t)((lane & 15)*144 + (lane & 16));

#define SUBSTEP(bw_, k16_) do { \
    const uint32_t sA_ = sbase + (bw_)*CSTG_B; \
    uint32_t ah_[2][4], al_[2][4], bh_[2][4], bl_[2][4]; \
    uint32_t aB_ = sA_ + aoff + (k16_)*2 + wm*32*80; \
    ldsm_x4(ah_[0], aB_);        ldsm_x4(ah_[1], aB_ + 16*80); \
    ldsm_x4(al_[0], aB_ + CA_B); ldsm_x4(al_[1], aB_ + CA_B + 16*80); \
    uint32_t bB_ = sA_ + 2*CA_B + voff + (k16_)*144 + (wn*32)*2; \
    _Pragma("unroll") \
    for (int n2_=0;n2_<2;n2_++){ ldsm_x4t(bh_[n2_], bB_ + n2_*32); \
                                 ldsm_x4t(bl_[n2_], bB_ + CB_B + n2_*32);} \
    _Pragma("unroll") \
    for (int mf_=0;mf_<2;mf_++) \
        _Pragma("unroll") \
        for (int nf_=0;nf_<4;nf_++){ \
            uint32_t b0_=bh_[nf_>>1][(nf_&1)*2], b1_=bh_[nf_>>1][(nf_&1)*2+1]; \
            uint32_t c0_=bl_[nf_>>1][(nf_&1)*2], c1_=bl_[nf_>>1][(nf_&1)*2+1]; \
            mma16816(acc[mf_][nf_], ah_[mf_], b0_, b1_); \
            mma16816(acc[mf_][nf_], ah_[mf_], c0_, c1_); \
            mma16816(acc[mf_][nf_], al_[mf_], b0_, b1_);} } while(0)

    LOADG(0);
    STORES(0);
    __syncthreads();

    const int tiles = SEQ >> 5;    // 32
    int buf = 0;
    for (int t = 0; t < tiles; t++) {
        if (t + 1 < tiles) LOADG((t + 1) * 32);
        SUBSTEP(buf, 0);
        SUBSTEP(buf, 16);
        if (t + 1 < tiles) {
            STORES(buf ^ 1);
            __syncthreads();
            buf ^= 1;
        }
    }
#undef LOADG
#undef STORES
#undef SUBSTEP

    __nv_bfloat16* Chz = Ch + (size_t)zb * SEQ * DMODEL + zh * 64;
    __nv_bfloat16* Clz = Cl + (size_t)zb * SEQ * DMODEL + zh * 64;
#pragma unroll
    for (int mf = 0; mf < 2; mf++) {
#pragma unroll
        for (int nf = 0; nf < 4; nf++) {
            const int row = m0 + wm*32 + mf*16 + rr;
            const int col = wn*32 + nf*8 + kc;
            float v0 = acc[mf][nf][0], v1 = acc[mf][nf][1];
            float v2 = acc[mf][nf][2], v3 = acc[mf][nf][3];
            __nv_bfloat162 h01, h23, l01, l23;
            h01.x = __float2bfloat16_rn(v0); h01.y = __float2bfloat16_rn(v1);
            h23.x = __float2bfloat16_rn(v2); h23.y = __float2bfloat16_rn(v3);
            l01.x = __float2bfloat16_rn(v0 - __bfloat162float(h01.x));
            l01.y = __float2bfloat16_rn(v1 - __bfloat162float(h01.y));
            l23.x = __float2bfloat16_rn(v2 - __bfloat162float(h23.x));
            l23.y = __float2bfloat16_rn(v3 - __bfloat162float(h23.y));
            *(__nv_bfloat162*)(Chz + (size_t)row*DMODEL + col)     = h01;
            *(__nv_bfloat162*)(Chz + (size_t)(row+8)*DMODEL + col) = h23;
            *(__nv_bfloat162*)(Clz + (size_t)row*DMODEL + col)     = l01;
            *(__nv_bfloat162*)(Clz + (size_t)(row+8)*DMODEL + col) = l23;
        }
    }
}

// ================= fp32 -> bf16 hi/lo split ==================================
__global__ void __launch_bounds__(256)
split_kernel(const float* __restrict__ in, __nv_bfloat16* __restrict__ hi,
             __nv_bfloat16* __restrict__ lo)
{
    const size_t i4 = ((size_t)blockIdx.x * 256 + threadIdx.x) * 4;
    float4 v = *(const float4*)(in + i4);
    __nv_bfloat162 H01, H23, L01, L23;
    H01.x = __float2bfloat16_rn(v.x); H01.y = __float2bfloat16_rn(v.y);
    H23.x = __float2bfloat16_rn(v.z); H23.y = __float2bfloat16_rn(v.w);
    L01.x = __float2bfloat16_rn(v.x - __bfloat162float(H01.x));
    L01.y = __float2bfloat16_rn(v.y - __bfloat162float(H01.y));
    L23.x = __float2bfloat16_rn(v.z - __bfloat162float(H23.x));
    L23.y = __float2bfloat16_rn(v.w - __bfloat162float(H23.y));
    *(__nv_bfloat162*)(hi + i4)     = H01;
    *(__nv_bfloat162*)(hi + i4 + 2) = H23;
    *(__nv_bfloat162*)(lo + i4)     = L01;
    *(__nv_bfloat162*)(lo + i4 + 2) = L23;
}

// ---------------- softmax: fp32 scores row -> split bf16 P -------------------
__device__ __forceinline__ float warpMax(float v) {
#pragma unroll
    for (int o = 16; o; o >>= 1) v = fmaxf(v, __shfl_xor_sync(0xffffffffu, v, o));
    return v;
}
__device__ __forceinline__ float warpSum(float v) {
#pragma unroll
    for (int o = 16; o; o >>= 1) v += __shfl_xor_sync(0xffffffffu, v, o);
    return v;
}

__global__ void __launch_bounds__(256)
softmax_split(const float* __restrict__ scores,
              __nv_bfloat16* __restrict__ ph, __nv_bfloat16* __restrict__ pl)
{
    const size_t rb = (size_t)blockIdx.x * SEQ;
    const int tid = threadIdx.x;
    __shared__ float sh[8];

    float4 xv = *(const float4*)(scores + rb + tid * 4);
    float x[4] = {xv.x, xv.y, xv.z, xv.w};

    float m = fmaxf(fmaxf(x[0], x[1]), fmaxf(x[2], x[3]));
    m = warpMax(m);
    if ((tid & 31) == 0) sh[tid >> 5] = m;
    __syncthreads();
    if (tid < 32) {
        float t = (tid < 8) ? sh[tid] : -INFINITY;
        t = warpMax(t);
        if (tid == 0) sh[0] = t;
    }
    __syncthreads();
    m = sh[0];
    __syncthreads();

    float s = 0.f;
#pragma unroll
    for (int j = 0; j < 4; j++) { x[j] = __expf(x[j] - m); s += x[j]; }
    s = warpSum(s);
    if ((tid & 31) == 0) sh[tid >> 5] = s;
    __syncthreads();
    if (tid < 32) {
        float t = (tid < 8) ? sh[tid] : 0.f;
        t = warpSum(t);
        if (tid == 0) sh[0] = t;
    }
    __syncthreads();
    const float inv = 1.0f / sh[0];

    float p0 = x[0]*inv, p1 = x[1]*inv, p2 = x[2]*inv, p3 = x[3]*inv;
    __nv_bfloat162 H01, H23, L01, L23;
    H01.x = __float2bfloat16_rn(p0); H01.y = __float2bfloat16_rn(p1);
    H23.x = __float2bfloat16_rn(p2); H23.y = __float2bfloat16_rn(p3);
    L01.x = __float2bfloat16_rn(p0 - __bfloat162float(H01.x));
    L01.y = __float2bfloat16_rn(p1 - __bfloat162float(H01.y));
    L23.x = __float2bfloat16_rn(p2 - __bfloat162float(H23.x));
    L23.y = __float2bfloat16_rn(p3 - __bfloat162float(H23.y));
    *(__nv_bfloat162*)(ph + rb + tid*4)     = H01;
    *(__nv_bfloat162*)(ph + rb + tid*4 + 2) = H23;
    *(__nv_bfloat162*)(pl + rb + tid*4)     = L01;
    *(__nv_bfloat162*)(pl + rb + tid*4 + 2) = L23;
}

// ---------------- residual add + LayerNorm -----------------------------------
__global__ void __launch_bounds__(256)
add_ln_kernel(const float* __restrict__ a, const float* __restrict__ b,
              const float* __restrict__ gamma, const float* __restrict__ beta,
              float* __restrict__ out)
{
    const size_t base = (size_t)blockIdx.x * DMODEL;
    const int tid = threadIdx.x;
    __shared__ float sh[8];

    float4 av = *(const float4*)(a + base + tid * 4);
    float4 bv = *(const float4*)(b + base + tid * 4);
    float v[4] = {av.x + bv.x, av.y + bv.y, av.z + bv.z, av.w + bv.w};

    float s = v[0] + v[1] + v[2] + v[3];
    s = warpSum(s);
    if ((tid & 31) == 0) sh[tid >> 5] = s;
    __syncthreads();
    if (tid < 32) {
        float t = (tid < 8) ? sh[tid] : 0.f;
        t = warpSum(t);
        if (tid == 0) sh[0] = t;
    }
    __syncthreads();
    float mu = sh[0] * (1.0f / DMODEL);
    __syncthreads();

    float sq = 0.f;
#pragma unroll
    for (int j = 0; j < 4; j++) { float d = v[j] - mu; sq += d * d; }
    sq = warpSum(sq);
    if ((tid & 31) == 0) sh[tid >> 5] = sq;
    __syncthreads();
    if (tid < 32) {
        float t = (tid < 8) ? sh[tid] : 0.f;
        t = warpSum(t);
        if (tid == 0) sh[0] = t;
    }
    __syncthreads();
    float rstd = rsqrtf(sh[0] * (1.0f / DMODEL) + EPS);

    float4 gv = *(const float4*)(gamma + tid * 4);
    float4 tv = *(const float4*)(beta + tid * 4);
    float4 o;
    o.x = (v[0] - mu) * rstd * gv.x + tv.x;
    o.y = (v[1] - mu) * rstd * gv.y + tv.y;
    o.z = (v[2] - mu) * rstd * gv.z + tv.z;
    o.w = (v[3] - mu) * rstd * gv.w + tv.w;
    *(float4*)(out + base + tid * 4) = o;
}

// ---------------- launch ------------------------------------------------------
extern "C" void kernel_launch(void* const* d_in, const int* in_sizes, int n_in,
                              void* d_out, int out_size)
{
    const float* src      = (const float*)d_in[0];
    const float* attnbias = (const float*)d_in[1];
    const float* Wqkv     = (const float*)d_in[2];
    const float* bqkv     = (const float*)d_in[3];
    const float* Wo       = (const float*)d_in[4];
    const float* bo       = (const float*)d_in[5];
    const float* g1       = (const float*)d_in[6];
    const float* b1n      = (const float*)d_in[7];
    const float* g2       = (const float*)d_in[8];
    const float* b2n      = (const float*)d_in[9];
    const float* W1       = (const float*)d_in[10];
    const float* b1       = (const float*)d_in[11];
    const float* W2       = (const float*)d_in[12];
    const float* b2       = (const float*)d_in[13];
    float* out = (float*)d_out;

    float *probs, *attnout, *x, *ffo;
    cudaGetSymbolAddress((void**)&probs,   g_probs);
    cudaGetSymbolAddress((void**)&attnout, g_attnout);
    cudaGetSymbolAddress((void**)&x,       g_x);
    cudaGetSymbolAddress((void**)&ffo,     g_ffo);

    __nv_bfloat16 *srcH,*srcL,*qkvH,*qkvL,*phH,*phL,*ctxH,*ctxL,*xH,*xL,*ffhH,*ffhL;
    __nv_bfloat16 *WqkvH,*WqkvL,*WoH,*WoL,*W1H,*W1L,*W2H,*W2L;
    cudaGetSymbolAddress((void**)&srcH, g_srcH);   cudaGetSymbolAddress((void**)&srcL, g_srcL);
    cudaGetSymbolAddress((void**)&qkvH, g_qkvH);   cudaGetSymbolAddress((void**)&qkvL, g_qkvL);
    cudaGetSymbolAddress((void**)&phH,  g_phH);    cudaGetSymbolAddress((void**)&phL,  g_phL);
    cudaGetSymbolAddress((void**)&ctxH, g_ctxH);   cudaGetSymbolAddress((void**)&ctxL, g_ctxL);
    cudaGetSymbolAddress((void**)&xH,   g_xH);     cudaGetSymbolAddress((void**)&xL,   g_xL);
    cudaGetSymbolAddress((void**)&ffhH, g_ffhH);   cudaGetSymbolAddress((void**)&ffhL, g_ffhL);
    cudaGetSymbolAddress((void**)&WqkvH,g_WqkvH);  cudaGetSymbolAddress((void**)&WqkvL,g_WqkvL);
    cudaGetSymbolAddress((void**)&WoH,  g_WoH);    cudaGetSymbolAddress((void**)&WoL,  g_WoL);
    cudaGetSymbolAddress((void**)&W1H,  g_W1H);    cudaGetSymbolAddress((void**)&W1L,  g_W1L);
    cudaGetSymbolAddress((void**)&W2H,  g_W2H);    cudaGetSymbolAddress((void**)&W2L,  g_W2L);

    cudaFuncSetAttribute(gemm_bf16s<0>, cudaFuncAttributeMaxDynamicSharedMemorySize, DSMEM);
    cudaFuncSetAttribute(gemm_bf16s<2>, cudaFuncAttributeMaxDynamicSharedMemorySize, DSMEM);
    cudaFuncSetAttribute(gemm_bf16s<4>, cudaFuncAttributeMaxDynamicSharedMemorySize, DSMEM);
    cudaFuncSetAttribute(gemm_bf16s<5>, cudaFuncAttributeMaxDynamicSharedMemorySize, DSMEM);
    cudaFuncSetAttribute(ctx_bf16s,     cudaFuncAttributeMaxDynamicSharedMemorySize, CSMEM);

    dim3 blk(256);
    const long ZA = (long)SEQ * 3072;          // qkv batch stride
    const long ZP = (long)SEQ * SEQ;           // probs per-head stride

    // operand splits
    split_kernel<<<MS*DMODEL/1024, blk>>>(src,  srcH, srcL);
    split_kernel<<<3*DMODEL*DMODEL/1024, blk>>>(Wqkv, WqkvH, WqkvL);
    split_kernel<<<DMODEL*DMODEL/1024, blk>>>(Wo,   WoH,   WoL);
    split_kernel<<<FFDIM*DMODEL/1024, blk>>>(W1,   W1H,   W1L);
    split_kernel<<<DMODEL*FFDIM/1024, blk>>>(W2,   W2H,   W2L);

    // 1) QKV = src @ Wqkv^T + bqkv -> split qkvH/L directly
    gemm_bf16s<4><<<dim3(24, 32, 1), blk, DSMEM>>>(
        srcH, srcL, WqkvH, WqkvL, nullptr, qkvH, qkvL,
        DMODEL, 3072,
        DMODEL, 0, 0,
        DMODEL, 0, 0,
        0, 0, 1, bqkv, 0, 0, 1.0f);

    // 2) scores = Q @ K^T * 0.125 + attn_bias -> fp32 probs
    gemm_bf16s<2><<<dim3(8, 8, 64), blk, DSMEM>>>(
        qkvH, qkvL, qkvH + DMODEL, qkvL + DMODEL, probs, nullptr, nullptr,
        HDIM, SEQ,
        3072, ZA, HDIM,
        3072, ZA, HDIM,
        (long)NHEAD * ZP, ZP, NHEAD,
        attnbias, ZP, SEQ, 0.125f);

    // 3) softmax -> split bf16 P
    softmax_split<<<BATCH * NHEAD * SEQ, blk>>>(probs, phH, phL);

    // 4) ctx = P @ V -> split ctxH/L
    ctx_bf16s<<<dim3(1, 8, 64), blk, CSMEM>>>(phH, phL,
        qkvH + 2*DMODEL, qkvL + 2*DMODEL, ctxH, ctxL);

    // 5) attn_out = ctx @ Wo^T + bo
    gemm_bf16s<0><<<dim3(8, 32, 1), blk, DSMEM>>>(
        ctxH, ctxL, WoH, WoL, attnout, nullptr, nullptr,
        DMODEL, DMODEL,
        DMODEL, 0, 0,
        DMODEL, 0, 0,
        0, 0, 1, bo, 0, 0, 1.0f);

    // 6) x = LN(src + attn_out)
    add_ln_kernel<<<MS, blk>>>(src, attnout, g1, b1n, x);
    split_kernel<<<MS*DMODEL/1024, blk>>>(x, xH, xL);

    // 7) ffh = gelu(x @ W1^T + b1) -> split ffhH/L directly
    gemm_bf16s<5><<<dim3(32, 32, 1), blk, DSMEM>>>(
        xH, xL, W1H, W1L, nullptr, ffhH, ffhL,
        DMODEL, FFDIM,
        DMODEL, 0, 0,
        DMODEL, 0, 0,
        0, 0, 1, b1, 0, 0, 1.0f);

    // 8) ffo = ffh @ W2^T + b2
    gemm_bf16s<0><<<dim3(8, 32, 1), blk, DSMEM>>>(
        ffhH, ffhL, W2H, W2L, ffo, nullptr, nullptr,
        FFDIM, DMODEL,
        FFDIM, 0, 0,
        FFDIM, 0, 0,
        0, 0, 1, b2, 0, 0, 1.0f);

    // 9) out = LN(x + ffo)
    add_ln_kernel<<<MS, blk>>>(x, ffo, g2, b2n, out);
}

// round 6
// speedup vs baseline: 4.1904x; 1.1001x over previous
#include <cuda_runtime.h>
#include <cuda_bf16.h>
#include <math.h>
#include <stdint.h>

// Problem constants
#define BATCH 4
#define SEQ   1024
#define DMODEL 1024
#define NHEAD 16
#define HDIM  64
#define FFDIM 4096
#define MS    (BATCH*SEQ)
#define EPS   1e-5f
#define LOG2E 1.4426950408889634f

// ---------------- scratch (device globals) -----------------------------------
__device__ float g_attnout[MS * DMODEL];
__device__ float g_x[MS * DMODEL];
__device__ float g_ffo[MS * DMODEL];

__device__ __nv_bfloat16 g_srcH[MS * DMODEL],  g_srcL[MS * DMODEL];
__device__ __nv_bfloat16 g_qkvH[MS * 3 * DMODEL], g_qkvL[MS * 3 * DMODEL];
__device__ __nv_bfloat16 g_ctxH[MS * DMODEL],  g_ctxL[MS * DMODEL];
__device__ __nv_bfloat16 g_xH[MS * DMODEL],    g_xL[MS * DMODEL];
__device__ __nv_bfloat16 g_ffhH[MS * FFDIM],   g_ffhL[MS * FFDIM];
__device__ __nv_bfloat16 g_WqkvH[3*DMODEL*DMODEL], g_WqkvL[3*DMODEL*DMODEL];
__device__ __nv_bfloat16 g_WoH[DMODEL*DMODEL],     g_WoL[DMODEL*DMODEL];
__device__ __nv_bfloat16 g_W1H[FFDIM*DMODEL],      g_W1L[FFDIM*DMODEL];
__device__ __nv_bfloat16 g_W2H[DMODEL*FFDIM],      g_W2L[DMODEL*FFDIM];

// ================= MMA helpers ================================================
__device__ __forceinline__ void mma16816(float* c, const uint32_t* a,
                                         uint32_t b0, uint32_t b1) {
    asm volatile(
        "mma.sync.aligned.m16n8k16.row.col.f32.bf16.bf16.f32 "
        "{%0,%1,%2,%3}, {%4,%5,%6,%7}, {%8,%9}, {%0,%1,%2,%3};"
        : "+f"(c[0]), "+f"(c[1]), "+f"(c[2]), "+f"(c[3])
        : "r"(a[0]), "r"(a[1]), "r"(a[2]), "r"(a[3]), "r"(b0), "r"(b1));
}
__device__ __forceinline__ void ldsm_x4(uint32_t* r, uint32_t addr) {
    asm volatile("ldmatrix.sync.aligned.m8n8.x4.shared.b16 {%0,%1,%2,%3}, [%4];"
        : "=r"(r[0]), "=r"(r[1]), "=r"(r[2]), "=r"(r[3]) : "r"(addr));
}
__device__ __forceinline__ void ldsm_x4t(uint32_t* r, uint32_t addr) {
    asm volatile("ldmatrix.sync.aligned.m8n8.x4.trans.shared.b16 {%0,%1,%2,%3}, [%4];"
        : "=r"(r[0]), "=r"(r[1]), "=r"(r[2]), "=r"(r[3]) : "r"(addr));
}
#define CP16(dst_, src_) \
    asm volatile("cp.async.cg.shared.global [%0], [%1], 16;" :: "r"(dst_), "l"(src_))
#define CP_COMMIT() asm volatile("cp.async.commit_group;" ::: "memory")
#define CP_WAIT0()  asm volatile("cp.async.wait_group 0;" ::: "memory")

__device__ __forceinline__ uint32_t packbf(float x, float y) {
    __nv_bfloat162 t; t.x = __float2bfloat16_rn(x); t.y = __float2bfloat16_rn(y);
    return *(uint32_t*)&t;
}
__device__ __forceinline__ void split2(float x, float y, uint32_t& hi, uint32_t& lo) {
    __nv_bfloat16 hx = __float2bfloat16_rn(x), hy = __float2bfloat16_rn(y);
    __nv_bfloat162 h; h.x = hx; h.y = hy;
    __nv_bfloat162 l;
    l.x = __float2bfloat16_rn(x - __bfloat162float(hx));
    l.y = __float2bfloat16_rn(y - __bfloat162float(hy));
    hi = *(uint32_t*)&h; lo = *(uint32_t*)&l;
}

#define PITCH 40
#define TILE_E (128*PITCH)
#define TILE_B (TILE_E*2)
#define STG_B  (4*TILE_B)
#define DSMEM  (2*STG_B)

// ================= dense bf16-split MMA GEMM =================================
// EPI: 0 +bias -> f32 ; 4 +bias -> split ; 5 gelu(+bias) -> split
template<int EPI>
__global__ void __launch_bounds__(256)
gemm_bf16s(const __nv_bfloat16* __restrict__ Ah, const __nv_bfloat16* __restrict__ Al,
           const __nv_bfloat16* __restrict__ Bh, const __nv_bfloat16* __restrict__ Bl,
           float* __restrict__ C, __nv_bfloat16* __restrict__ Ch, __nv_bfloat16* __restrict__ Cl,
           int K, int cRS, long aRS, long bRS,
           const float* __restrict__ bias)
{
    extern __shared__ char smc[];
    __nv_bfloat16* sm = (__nv_bfloat16*)smc;
    const uint32_t sbase = (uint32_t)__cvta_generic_to_shared(smc);

    const int tid = threadIdx.x, wid = tid >> 5, lane = tid & 31;
    const int m0 = blockIdx.y * 128, n0 = blockIdx.x * 128;
    const int wm = wid & 3, wn = wid >> 2;
    const int rr = lane >> 2, kc = (lane & 3) * 2;

    const __nv_bfloat16* pAh = Ah + (size_t)m0*aRS;
    const __nv_bfloat16* pAl = Al + (size_t)m0*aRS;
    const __nv_bfloat16* pBh = Bh + (size_t)n0*bRS;
    const __nv_bfloat16* pBl = Bl + (size_t)n0*bRS;

    float acc[2][8][4];
#pragma unroll
    for (int i=0;i<2;i++)
#pragma unroll
        for (int j=0;j<8;j++)
#pragma unroll
            for (int q=0;q<4;q++) acc[i][j][q]=0.f;

    uint4 rg[8];
    const int lrow = tid >> 2, lseg = tid & 3;

#define LOADG(kof_) do { \
    _Pragma("unroll") \
    for (int j_=0;j_<2;j_++){ int row_=lrow+64*j_; \
        size_t ga_=(size_t)row_*aRS+(kof_)+lseg*8; \
        size_t gb_=(size_t)row_*bRS+(kof_)+lseg*8; \
        rg[j_]   = *(const uint4*)(pAh+ga_); rg[2+j_]=*(const uint4*)(pAl+ga_); \
        rg[4+j_] = *(const uint4*)(pBh+gb_); rg[6+j_]=*(const uint4*)(pBl+gb_);} } while(0)

#define STORES(bw_) do { \
    __nv_bfloat16* sp_ = sm + (bw_)*(STG_B/2); \
    _Pragma("unroll") \
    for (int j_=0;j_<2;j_++){ int row_=lrow+64*j_; int off_=row_*PITCH+lseg*8; \
        *(uint4*)(sp_+off_)=rg[j_];            *(uint4*)(sp_+TILE_E+off_)=rg[2+j_]; \
        *(uint4*)(sp_+2*TILE_E+off_)=rg[4+j_]; *(uint4*)(sp_+3*TILE_E+off_)=rg[6+j_];} } while(0)

    const uint32_t aoff = (uint32_t)((lane & 15)*80 + (lane & 16));
    const uint32_t boff = (uint32_t)((((lane & 16) >> 1) + (lane & 7))*80 + ((lane & 8) ? 16 : 0));

#define SUBSTEP(bw_, k16_) do { \
    const uint32_t sA_ = sbase + (bw_)*STG_B; \
    uint32_t ah_[2][4], al_[2][4], bh_[4][4], bl_[4][4]; \
    uint32_t aB_ = sA_ + aoff + (k16_)*2 + wm*32*80; \
    ldsm_x4(ah_[0], aB_);          ldsm_x4(ah_[1], aB_ + 16*80); \
    ldsm_x4(al_[0], aB_ + TILE_B); ldsm_x4(al_[1], aB_ + TILE_B + 16*80); \
    uint32_t bB_ = sA_ + 2*TILE_B + boff + (k16_)*2 + wn*64*80; \
    _Pragma("unroll") \
    for (int n2_=0;n2_<4;n2_++){ ldsm_x4(bh_[n2_], bB_ + n2_*16*80); \
                                 ldsm_x4(bl_[n2_], bB_ + TILE_B + n2_*16*80);} \
    _Pragma("unroll") \
    for (int mf_=0;mf_<2;mf_++) \
        _Pragma("unroll") \
        for (int nf_=0;nf_<8;nf_++){ \
            uint32_t b0_=bh_[nf_>>1][(nf_&1)*2], b1_=bh_[nf_>>1][(nf_&1)*2+1]; \
            uint32_t c0_=bl_[nf_>>1][(nf_&1)*2], c1_=bl_[nf_>>1][(nf_&1)*2+1]; \
            mma16816(acc[mf_][nf_], ah_[mf_], b0_, b1_); \
            mma16816(acc[mf_][nf_], ah_[mf_], c0_, c1_); \
            mma16816(acc[mf_][nf_], al_[mf_], b0_, b1_);} } while(0)

    LOADG(0);
    STORES(0);
    __syncthreads();

    const int tiles = K >> 5;
    int buf = 0;
    for (int t = 0; t < tiles; t++) {
        if (t + 1 < tiles) LOADG((t + 1) * 32);
        SUBSTEP(buf, 0);
        SUBSTEP(buf, 16);
        if (t + 1 < tiles) {
            STORES(buf ^ 1);
            __syncthreads();
            buf ^= 1;
        }
    }
#undef LOADG
#undef STORES
#undef SUBSTEP

#pragma unroll
    for (int mf = 0; mf < 2; mf++) {
#pragma unroll
        for (int nf = 0; nf < 8; nf++) {
            const int row = m0 + wm*32 + mf*16 + rr;
            const int col = n0 + wn*64 + nf*8 + kc;
            float b0 = bias[col], b1 = bias[col+1];
            float v0 = acc[mf][nf][0]+b0, v1 = acc[mf][nf][1]+b1;
            float v2 = acc[mf][nf][2]+b0, v3 = acc[mf][nf][3]+b1;
            if (EPI == 5) {
                v0 = 0.5f*v0*(1.0f+erff(v0*0.70710678118654752f));
                v1 = 0.5f*v1*(1.0f+erff(v1*0.70710678118654752f));
                v2 = 0.5f*v2*(1.0f+erff(v2*0.70710678118654752f));
                v3 = 0.5f*v3*(1.0f+erff(v3*0.70710678118654752f));
            }
            if (EPI == 0) {
                *(float2*)(C + (size_t)row*cRS + col)     = make_float2(v0, v1);
                *(float2*)(C + (size_t)(row+8)*cRS + col) = make_float2(v2, v3);
            } else {
                uint32_t h01, l01, h23, l23;
                split2(v0, v1, h01, l01);
                split2(v2, v3, h23, l23);
                *(uint32_t*)(Ch + (size_t)row*cRS + col)     = h01;
                *(uint32_t*)(Ch + (size_t)(row+8)*cRS + col) = h23;
                *(uint32_t*)(Cl + (size_t)row*cRS + col)     = l01;
                *(uint32_t*)(Cl + (size_t)(row+8)*cRS + col) = l23;
            }
        }
    }
}

// ================= fused flash attention ====================================
// grid (8 m-tiles, 64 z). 8 warps, each owns 16 rows, full 128-col strip per
// 64-wide KV block. Online softmax; P hi/lo repacked in registers; O += P@V.
#define FQP_B 144                       // 72 bf16 pitch
#define FK_B  9216                      // 64 x 72 x 2
#define FB_P  272                       // bias pitch bytes (68 floats)
#define FB_B  34816                     // 128 x 272
#define FSTG_B (4*FK_B + FB_B)          // 71680
#define FQ_B  36864                     // Qh+Ql
#define FSMEM (FQ_B + 2*FSTG_B)         // 180224

__global__ void __launch_bounds__(256)
flash_attn(const __nv_bfloat16* __restrict__ qkvH, const __nv_bfloat16* __restrict__ qkvL,
           const float* __restrict__ attnbias,
           __nv_bfloat16* __restrict__ Ch, __nv_bfloat16* __restrict__ Cl)
{
    extern __shared__ char smc[];
    const uint32_t sbase = (uint32_t)__cvta_generic_to_shared(smc);
    const int tid = threadIdx.x, wid = tid >> 5, lane = tid & 31;
    const int m0 = blockIdx.x * 128;
    const int z = blockIdx.y, zb = z >> 4, zh = z & 15;
    const int rr = lane >> 2, kc = (lane & 3) * 2;

    const size_t qbase = (size_t)zb * SEQ * 3072 + (size_t)zh * 64;
    const __nv_bfloat16* gQh = qkvH + qbase;
    const __nv_bfloat16* gQl = qkvL + qbase;
    const __nv_bfloat16* gKh = qkvH + qbase + DMODEL;
    const __nv_bfloat16* gKl = qkvL + qbase + DMODEL;
    const __nv_bfloat16* gVh = qkvH + qbase + 2*DMODEL;
    const __nv_bfloat16* gVl = qkvL + qbase + 2*DMODEL;
    const float* gB = attnbias + (size_t)zh * SEQ * SEQ + (size_t)m0 * SEQ;

    // issue stage j's cp.async loads
#define ISSUE(j_) do { \
    const uint32_t sb_ = sbase + FQ_B + ((j_)&1)*FSTG_B; \
    const int s0_ = (j_)*64; \
    _Pragma("unroll") \
    for (int it_=0; it_<16; it_++){ int i_ = tid + it_*256; \
        if (i_ < 2048) { \
            int t_ = i_ >> 9;                 /* 0 Kh,1 Kl,2 Vh,3 Vl */ \
            int idx_ = i_ & 511; int row_ = idx_>>3, seg_ = idx_&7; \
            const __nv_bfloat16* s_; \
            if (t_==0) s_ = gKh; else if (t_==1) s_ = gKl; \
            else if (t_==2) s_ = gVh; else s_ = gVl; \
            CP16(sb_ + t_*FK_B + row_*FQP_B + seg_*16, \
                 s_ + (size_t)(s0_+row_)*3072 + seg_*8); \
        } else { \
            int ib_ = i_ - 2048; int row_ = ib_>>4, seg_ = ib_&15; \
            CP16(sb_ + 4*FK_B + row_*FB_P + seg_*16, \
                 gB + (size_t)row_*SEQ + s0_ + seg_*4); \
        } } } while (0)

    ISSUE(0);
    CP_COMMIT();

    // Q tile load (plain): 128 x 64 h/l, pitch 72
    for (int i = tid; i < 2048; i += 256) {
        int t = i >> 10, idx = i & 1023, row = idx >> 3, seg = idx & 7;
        const __nv_bfloat16* s = t ? gQl : gQh;
        uint4 v = *(const uint4*)(s + (size_t)(m0+row)*3072 + seg*8);
        *(uint4*)(smc + t*18432 + row*FQP_B + seg*16) = v;
    }
    __syncthreads();

    // preload Q fragments (A m16k16, 4 k-steps)
    const uint32_t aoff = (uint32_t)((lane & 15)*FQP_B + (lane & 16));
    uint32_t qh[4][4], ql[4][4];
    {
        uint32_t qB = sbase + aoff + wid*16*FQP_B;
#pragma unroll
        for (int ks = 0; ks < 4; ks++) {
            ldsm_x4(qh[ks], qB + ks*32);
            ldsm_x4(ql[ks], qB + 18432 + ks*32);
        }
    }

    const uint32_t boff = (uint32_t)((((lane & 16) >> 1) + (lane & 7))*FQP_B + ((lane & 8) ? 16 : 0));
    const uint32_t voff = (uint32_t)((lane & 15)*FQP_B + (lane & 16));

    float O[8][4];
#pragma unroll
    for (int j=0;j<8;j++)
#pragma unroll
        for (int q=0;q<4;q++) O[j][q]=0.f;
    float mrow0 = -INFINITY, mrow1 = -INFINITY, lrow0 = 0.f, lrow1 = 0.f;

    for (int j = 0; j < 16; j++) {
        CP_WAIT0();
        __syncthreads();
        if (j + 1 < 16) { ISSUE(j + 1); CP_COMMIT(); }

        const uint32_t stg = sbase + FQ_B + (j&1)*FSTG_B;
        const char* stgp = smc + FQ_B + (j&1)*FSTG_B;

        // ---- S = Q @ K^T (3-term split) ----
        float s[8][4];
#pragma unroll
        for (int nf=0;nf<8;nf++)
#pragma unroll
            for (int q=0;q<4;q++) s[nf][q]=0.f;
#pragma unroll
        for (int ks = 0; ks < 4; ks++) {
            uint32_t kh[4][4], kl[4][4];
            uint32_t kB = stg + boff + ks*32;
#pragma unroll
            for (int nb=0;nb<4;nb++){
                ldsm_x4(kh[nb], kB + nb*16*FQP_B);
                ldsm_x4(kl[nb], kB + FK_B + nb*16*FQP_B);
            }
#pragma unroll
            for (int nf=0;nf<8;nf++){
                uint32_t b0=kh[nf>>1][(nf&1)*2], b1=kh[nf>>1][(nf&1)*2+1];
                uint32_t c0=kl[nf>>1][(nf&1)*2], c1=kl[nf>>1][(nf&1)*2+1];
                mma16816(s[nf], qh[ks], b0, b1);
                mma16816(s[nf], qh[ks], c0, c1);
                mma16816(s[nf], ql[ks], b0, b1);
            }
        }

        // ---- scale + bias ----
        const char* bp = stgp + 4*FK_B;
        const int r0 = wid*16 + rr;
#pragma unroll
        for (int nf=0;nf<8;nf++){
            float2 q0 = *(const float2*)(bp + r0*FB_P + (nf*8+kc)*4);
            float2 q1 = *(const float2*)(bp + (r0+8)*FB_P + (nf*8+kc)*4);
            s[nf][0] = fmaf(s[nf][0], 0.125f, q0.x);
            s[nf][1] = fmaf(s[nf][1], 0.125f, q0.y);
            s[nf][2] = fmaf(s[nf][2], 0.125f, q1.x);
            s[nf][3] = fmaf(s[nf][3], 0.125f, q1.y);
        }

        // ---- online softmax ----
        float mx0 = -INFINITY, mx1 = -INFINITY;
#pragma unroll
        for (int nf=0;nf<8;nf++){
            mx0 = fmaxf(mx0, fmaxf(s[nf][0], s[nf][1]));
            mx1 = fmaxf(mx1, fmaxf(s[nf][2], s[nf][3]));
        }
        mx0 = fmaxf(mx0, __shfl_xor_sync(0xffffffffu, mx0, 1));
        mx0 = fmaxf(mx0, __shfl_xor_sync(0xffffffffu, mx0, 2));
        mx1 = fmaxf(mx1, __shfl_xor_sync(0xffffffffu, mx1, 1));
        mx1 = fmaxf(mx1, __shfl_xor_sync(0xffffffffu, mx1, 2));
        float mn0 = fmaxf(mrow0, mx0), mn1 = fmaxf(mrow1, mx1);
        float a0 = exp2f((mrow0 - mn0)*LOG2E), a1 = exp2f((mrow1 - mn1)*LOG2E);
        mrow0 = mn0; mrow1 = mn1;

        float rs0 = 0.f, rs1 = 0.f;
#pragma unroll
        for (int nf=0;nf<8;nf++){
            s[nf][0] = exp2f((s[nf][0]-mn0)*LOG2E);
            s[nf][1] = exp2f((s[nf][1]-mn0)*LOG2E);
            s[nf][2] = exp2f((s[nf][2]-mn1)*LOG2E);
            s[nf][3] = exp2f((s[nf][3]-mn1)*LOG2E);
            rs0 += s[nf][0] + s[nf][1];
            rs1 += s[nf][2] + s[nf][3];
        }
        lrow0 = lrow0*a0 + rs0;
        lrow1 = lrow1*a1 + rs1;

        // ---- pack P into A fragments (hi/lo) ----
        uint32_t ph[4][4], pl[4][4];
#pragma unroll
        for (int ks=0;ks<4;ks++){
            const float* pe = s[2*ks];
            const float* po = s[2*ks+1];
            split2(pe[0], pe[1], ph[ks][0], pl[ks][0]);
            split2(pe[2], pe[3], ph[ks][1], pl[ks][1]);
            split2(po[0], po[1], ph[ks][2], pl[ks][2]);
            split2(po[2], po[3], ph[ks][3], pl[ks][3]);
        }

        // ---- O = O*alpha + P @ V ----
#pragma unroll
        for (int nf=0;nf<8;nf++){
            O[nf][0] *= a0; O[nf][1] *= a0;
            O[nf][2] *= a1; O[nf][3] *= a1;
        }
#pragma unroll
        for (int ks = 0; ks < 4; ks++) {
            uint32_t vh[4][4], vl[4][4];
            uint32_t vB = stg + 2*FK_B + voff + ks*16*FQP_B;
#pragma unroll
            for (int nb=0;nb<4;nb++){
                ldsm_x4t(vh[nb], vB + nb*32);
                ldsm_x4t(vl[nb], vB + FK_B + nb*32);
            }
#pragma unroll
            for (int nf=0;nf<8;nf++){
                uint32_t b0=vh[nf>>1][(nf&1)*2], b1=vh[nf>>1][(nf&1)*2+1];
                uint32_t c0=vl[nf>>1][(nf&1)*2], c1=vl[nf>>1][(nf&1)*2+1];
                mma16816(O[nf], ph[ks], b0, b1);
                mma16816(O[nf], ph[ks], c0, c1);
                mma16816(O[nf], pl[ks], b0, b1);
            }
        }
    }
#undef ISSUE

    // ---- finalize: O / l, split-store to ctx ----
    lrow0 += __shfl_xor_sync(0xffffffffu, lrow0, 1);
    lrow0 += __shfl_xor_sync(0xffffffffu, lrow0, 2);
    lrow1 += __shfl_xor_sync(0xffffffffu, lrow1, 1);
    lrow1 += __shfl_xor_sync(0xffffffffu, lrow1, 2);
    const float inv0 = 1.0f / lrow0, inv1 = 1.0f / lrow1;

    const size_t row0 = (size_t)zb*SEQ + m0 + wid*16 + rr;
#pragma unroll
    for (int nf=0;nf<8;nf++){
        const int col = zh*64 + nf*8 + kc;
        uint32_t h01, l01, h23, l23;
        split2(O[nf][0]*inv0, O[nf][1]*inv0, h01, l01);
        split2(O[nf][2]*inv1, O[nf][3]*inv1, h23, l23);
        *(uint32_t*)(Ch + row0*DMODEL + col)     = h01;
        *(uint32_t*)(Ch + (row0+8)*DMODEL + col) = h23;
        *(uint32_t*)(Cl + row0*DMODEL + col)     = l01;
        *(uint32_t*)(Cl + (row0+8)*DMODEL + col) = l23;
    }
}

// ================= fp32 -> bf16 hi/lo split ==================================
__global__ void __launch_bounds__(256)
split_kernel(const float* __restrict__ in, __nv_bfloat16* __restrict__ hi,
             __nv_bfloat16* __restrict__ lo)
{
    const size_t i4 = ((size_t)blockIdx.x * 256 + threadIdx.x) * 4;
    float4 v = *(const float4*)(in + i4);
    uint32_t h01, l01, h23, l23;
    split2(v.x, v.y, h01, l01);
    split2(v.z, v.w, h23, l23);
    *(uint32_t*)(hi + i4)     = h01;
    *(uint32_t*)(hi + i4 + 2) = h23;
    *(uint32_t*)(lo + i4)     = l01;
    *(uint32_t*)(lo + i4 + 2) = l23;
}

// ---------------- residual add + LayerNorm (optional fused split) ------------
__device__ __forceinline__ float warpSum(float v) {
#pragma unroll
    for (int o = 16; o; o >>= 1) v += __shfl_xor_sync(0xffffffffu, v, o);
    return v;
}

template<bool SPLIT>
__global__ void __launch_bounds__(256)
add_ln_kernel(const float* __restrict__ a, const float* __restrict__ b,
              const float* __restrict__ gamma, const float* __restrict__ beta,
              float* __restrict__ out,
              __nv_bfloat16* __restrict__ oh, __nv_bfloat16* __restrict__ ol)
{
    const size_t base = (size_t)blockIdx.x * DMODEL;
    const int tid = threadIdx.x;
    __shared__ float sh[8];

    float4 av = *(const float4*)(a + base + tid * 4);
    float4 bv = *(const float4*)(b + base + tid * 4);
    float v[4] = {av.x + bv.x, av.y + bv.y, av.z + bv.z, av.w + bv.w};

    float s = v[0] + v[1] + v[2] + v[3];
    s = warpSum(s);
    if ((tid & 31) == 0) sh[tid >> 5] = s;
    __syncthreads();
    if (tid < 32) {
        float t = (tid < 8) ? sh[tid] : 0.f;
        t = warpSum(t);
        if (tid == 0) sh[0] = t;
    }
    __syncthreads();
    float mu = sh[0] * (1.0f / DMODEL);
    __syncthreads();

    float sq = 0.f;
#pragma unroll
    for (int j = 0; j < 4; j++) { float d = v[j] - mu; sq += d * d; }
    sq = warpSum(sq);
    if ((tid & 31) == 0) sh[tid >> 5] = sq;
    __syncthreads();
    if (tid < 32) {
        float t = (tid < 8) ? sh[tid] : 0.f;
        t = warpSum(t);
        if (tid == 0) sh[0] = t;
    }
    __syncthreads();
    float rstd = rsqrtf(sh[0] * (1.0f / DMODEL) + EPS);

    float4 gv = *(const float4*)(gamma + tid * 4);
    float4 tv = *(const float4*)(beta + tid * 4);
    float o0 = (v[0] - mu) * rstd * gv.x + tv.x;
    float o1 = (v[1] - mu) * rstd * gv.y + tv.y;
    float o2 = (v[2] - mu) * rstd * gv.z + tv.z;
    float o3 = (v[3] - mu) * rstd * gv.w + tv.w;
    *(float4*)(out + base + tid * 4) = make_float4(o0, o1, o2, o3);
    if (SPLIT) {
        uint32_t h01, l01, h23, l23;
        split2(o0, o1, h01, l01);
        split2(o2, o3, h23, l23);
        *(uint32_t*)(oh + base + tid*4)     = h01;
        *(uint32_t*)(oh + base + tid*4 + 2) = h23;
        *(uint32_t*)(ol + base + tid*4)     = l01;
        *(uint32_t*)(ol + base + tid*4 + 2) = l23;
    }
}

// ---------------- launch ------------------------------------------------------
extern "C" void kernel_launch(void* const* d_in, const int* in_sizes, int n_in,
                              void* d_out, int out_size)
{
    const float* src      = (const float*)d_in[0];
    const float* attnbias = (const float*)d_in[1];
    const float* Wqkv     = (const float*)d_in[2];
    const float* bqkv     = (const float*)d_in[3];
    const float* Wo       = (const float*)d_in[4];
    const float* bo       = (const float*)d_in[5];
    const float* g1       = (const float*)d_in[6];
    const float* b1n      = (const float*)d_in[7];
    const float* g2       = (const float*)d_in[8];
    const float* b2n      = (const float*)d_in[9];
    const float* W1       = (const float*)d_in[10];
    const float* b1       = (const float*)d_in[11];
    const float* W2       = (const float*)d_in[12];
    const float* b2       = (const float*)d_in[13];
    float* out = (float*)d_out;

    float *attnout, *x, *ffo;
    cudaGetSymbolAddress((void**)&attnout, g_attnout);
    cudaGetSymbolAddress((void**)&x,       g_x);
    cudaGetSymbolAddress((void**)&ffo,     g_ffo);

    __nv_bfloat16 *srcH,*srcL,*qkvH,*qkvL,*ctxH,*ctxL,*xH,*xL,*ffhH,*ffhL;
    __nv_bfloat16 *WqkvH,*WqkvL,*WoH,*WoL,*W1H,*W1L,*W2H,*W2L;
    cudaGetSymbolAddress((void**)&srcH, g_srcH);   cudaGetSymbolAddress((void**)&srcL, g_srcL);
    cudaGetSymbolAddress((void**)&qkvH, g_qkvH);   cudaGetSymbolAddress((void**)&qkvL, g_qkvL);
    cudaGetSymbolAddress((void**)&ctxH, g_ctxH);   cudaGetSymbolAddress((void**)&ctxL, g_ctxL);
    cudaGetSymbolAddress((void**)&xH,   g_xH);     cudaGetSymbolAddress((void**)&xL,   g_xL);
    cudaGetSymbolAddress((void**)&ffhH, g_ffhH);   cudaGetSymbolAddress((void**)&ffhL, g_ffhL);
    cudaGetSymbolAddress((void**)&WqkvH,g_WqkvH);  cudaGetSymbolAddress((void**)&WqkvL,g_WqkvL);
    cudaGetSymbolAddress((void**)&WoH,  g_WoH);    cudaGetSymbolAddress((void**)&WoL,  g_WoL);
    cudaGetSymbolAddress((void**)&W1H,  g_W1H);    cudaGetSymbolAddress((void**)&W1L,  g_W1L);
    cudaGetSymbolAddress((void**)&W2H,  g_W2H);    cudaGetSymbolAddress((void**)&W2L,  g_W2L);

    cudaFuncSetAttribute(gemm_bf16s<0>, cudaFuncAttributeMaxDynamicSharedMemorySize, DSMEM);
    cudaFuncSetAttribute(gemm_bf16s<4>, cudaFuncAttributeMaxDynamicSharedMemorySize, DSMEM);
    cudaFuncSetAttribute(gemm_bf16s<5>, cudaFuncAttributeMaxDynamicSharedMemorySize, DSMEM);
    cudaFuncSetAttribute(flash_attn,    cudaFuncAttributeMaxDynamicSharedMemorySize, FSMEM);

    dim3 blk(256);

    // operand splits
    split_kernel<<<MS*DMODEL/1024, blk>>>(src,  srcH, srcL);
    split_kernel<<<3*DMODEL*DMODEL/1024, blk>>>(Wqkv, WqkvH, WqkvL);
    split_kernel<<<DMODEL*DMODEL/1024, blk>>>(Wo,   WoH,   WoL);
    split_kernel<<<FFDIM*DMODEL/1024, blk>>>(W1,   W1H,   W1L);
    split_kernel<<<DMODEL*FFDIM/1024, blk>>>(W2,   W2H,   W2L);

    // 1) QKV = src @ Wqkv^T + bqkv -> split qkvH/L
    gemm_bf16s<4><<<dim3(24, 32), blk, DSMEM>>>(
        srcH, srcL, WqkvH, WqkvL, nullptr, qkvH, qkvL,
        DMODEL, 3072, DMODEL, DMODEL, bqkv);

    // 2-4) fused attention -> split ctxH/L
    flash_attn<<<dim3(8, 64), blk, FSMEM>>>(qkvH, qkvL, attnbias, ctxH, ctxL);

    // 5) attn_out = ctx @ Wo^T + bo
    gemm_bf16s<0><<<dim3(8, 32), blk, DSMEM>>>(
        ctxH, ctxL, WoH, WoL, attnout, nullptr, nullptr,
        DMODEL, DMODEL, DMODEL, DMODEL, bo);

    // 6) x = LN(src + attn_out)  (+ fused split)
    add_ln_kernel<true><<<MS, blk>>>(src, attnout, g1, b1n, x, xH, xL);

    // 7) ffh = gelu(x @ W1^T + b1) -> split ffhH/L
    gemm_bf16s<5><<<dim3(32, 32), blk, DSMEM>>>(
        xH, xL, W1H, W1L, nullptr, ffhH, ffhL,
        DMODEL, FFDIM, DMODEL, DMODEL, b1);

    // 8) ffo = ffh @ W2^T + b2
    gemm_bf16s<0><<<dim3(8, 32), blk, DSMEM>>>(
        ffhH, ffhL, W2H, W2L, ffo, nullptr, nullptr,
        FFDIM, DMODEL, FFDIM, FFDIM, b2);

    // 9) out = LN(x + ffo)
    add_ln_kernel<false><<<MS, blk>>>(x, ffo, g2, b2n, out, nullptr, nullptr);
}

// round 7
// speedup vs baseline: 4.5204x; 1.0788x over previous
#include <cuda_runtime.h>
#include <cuda_bf16.h>
#include <math.h>
#include <stdint.h>

// Problem constants
#define BATCH 4
#define SEQ   1024
#define DMODEL 1024
#define NHEAD 16
#define HDIM  64
#define FFDIM 4096
#define MS    (BATCH*SEQ)
#define EPS   1e-5f
#define LOG2E 1.4426950408889634f

// ---------------- scratch (device globals) -----------------------------------
__device__ float g_attnout[MS * DMODEL];
__device__ float g_x[MS * DMODEL];
__device__ float g_ffo[MS * DMODEL];

__device__ __nv_bfloat16 g_srcH[MS * DMODEL],  g_srcL[MS * DMODEL];
__device__ __nv_bfloat16 g_qkvH[MS * 3 * DMODEL], g_qkvL[MS * 3 * DMODEL];
__device__ __nv_bfloat16 g_ctxH[MS * DMODEL],  g_ctxL[MS * DMODEL];
__device__ __nv_bfloat16 g_xH[MS * DMODEL],    g_xL[MS * DMODEL];
__device__ __nv_bfloat16 g_ffhH[MS * FFDIM],   g_ffhL[MS * FFDIM];
__device__ __nv_bfloat16 g_WqkvH[3*DMODEL*DMODEL], g_WqkvL[3*DMODEL*DMODEL];
__device__ __nv_bfloat16 g_WoH[DMODEL*DMODEL],     g_WoL[DMODEL*DMODEL];
__device__ __nv_bfloat16 g_W1H[FFDIM*DMODEL],      g_W1L[FFDIM*DMODEL];
__device__ __nv_bfloat16 g_W2H[DMODEL*FFDIM],      g_W2L[DMODEL*FFDIM];

// ================= MMA helpers ================================================
__device__ __forceinline__ void mma16816(float* c, const uint32_t* a,
                                         uint32_t b0, uint32_t b1) {
    asm volatile(
        "mma.sync.aligned.m16n8k16.row.col.f32.bf16.bf16.f32 "
        "{%0,%1,%2,%3}, {%4,%5,%6,%7}, {%8,%9}, {%0,%1,%2,%3};"
        : "+f"(c[0]), "+f"(c[1]), "+f"(c[2]), "+f"(c[3])
        : "r"(a[0]), "r"(a[1]), "r"(a[2]), "r"(a[3]), "r"(b0), "r"(b1));
}
__device__ __forceinline__ void ldsm_x4(uint32_t* r, uint32_t addr) {
    asm volatile("ldmatrix.sync.aligned.m8n8.x4.shared.b16 {%0,%1,%2,%3}, [%4];"
        : "=r"(r[0]), "=r"(r[1]), "=r"(r[2]), "=r"(r[3]) : "r"(addr));
}
__device__ __forceinline__ void ldsm_x4t(uint32_t* r, uint32_t addr) {
    asm volatile("ldmatrix.sync.aligned.m8n8.x4.trans.shared.b16 {%0,%1,%2,%3}, [%4];"
        : "=r"(r[0]), "=r"(r[1]), "=r"(r[2]), "=r"(r[3]) : "r"(addr));
}
#define CP16(dst_, src_) \
    asm volatile("cp.async.cg.shared.global [%0], [%1], 16;" :: "r"(dst_), "l"(src_))
#define CP_COMMIT() asm volatile("cp.async.commit_group;" ::: "memory")
#define CP_WAIT1()  asm volatile("cp.async.wait_group 1;" ::: "memory")
#define CP_WAIT2()  asm volatile("cp.async.wait_group 2;" ::: "memory")

__device__ __forceinline__ void split2(float x, float y, uint32_t& hi, uint32_t& lo) {
    __nv_bfloat16 hx = __float2bfloat16_rn(x), hy = __float2bfloat16_rn(y);
    __nv_bfloat162 h; h.x = hx; h.y = hy;
    __nv_bfloat162 l;
    l.x = __float2bfloat16_rn(x - __bfloat162float(hx));
    l.y = __float2bfloat16_rn(y - __bfloat162float(hy));
    hi = *(uint32_t*)&h; lo = *(uint32_t*)&l;
}

#define PITCH 40
#define TILE_E (128*PITCH)
#define TILE_B (TILE_E*2)
#define STG_B  (4*TILE_B)
#define DSMEM  (2*STG_B)

// ================= dense bf16-split MMA GEMM (cp.async, 2 CTA/SM) ============
// EPI: 0 +bias -> f32 ; 4 +bias -> split ; 5 gelu(+bias) -> split
template<int EPI>
__global__ void __launch_bounds__(256, 2)
gemm_bf16s(const __nv_bfloat16* __restrict__ Ah, const __nv_bfloat16* __restrict__ Al,
           const __nv_bfloat16* __restrict__ Bh, const __nv_bfloat16* __restrict__ Bl,
           float* __restrict__ C, __nv_bfloat16* __restrict__ Ch, __nv_bfloat16* __restrict__ Cl,
           int K, int cRS, long aRS, long bRS,
           const float* __restrict__ bias)
{
    extern __shared__ char smc[];
    const uint32_t sbase = (uint32_t)__cvta_generic_to_shared(smc);

    const int tid = threadIdx.x, wid = tid >> 5, lane = tid & 31;
    const int m0 = blockIdx.y * 128, n0 = blockIdx.x * 128;
    const int wm = wid & 3, wn = wid >> 2;
    const int rr = lane >> 2, kc = (lane & 3) * 2;

    const __nv_bfloat16* pAh = Ah + (size_t)m0*aRS;
    const __nv_bfloat16* pAl = Al + (size_t)m0*aRS;
    const __nv_bfloat16* pBh = Bh + (size_t)n0*bRS;
    const __nv_bfloat16* pBl = Bl + (size_t)n0*bRS;

    float acc[2][8][4];
#pragma unroll
    for (int i=0;i<2;i++)
#pragma unroll
        for (int j=0;j<8;j++)
#pragma unroll
            for (int q=0;q<4;q++) acc[i][j][q]=0.f;

    const int lrow = tid >> 2, lseg = tid & 3;

#define ISSUED(kof_, bw_) do { \
    uint32_t sp_ = sbase + (bw_)*STG_B; \
    _Pragma("unroll") \
    for (int j_=0;j_<2;j_++){ int row_=lrow+64*j_; uint32_t off_=row_*80+lseg*16; \
        size_t ga_=(size_t)row_*aRS+(kof_)+lseg*8; \
        size_t gb_=(size_t)row_*bRS+(kof_)+lseg*8; \
        CP16(sp_+off_,          pAh+ga_); CP16(sp_+TILE_B+off_,   pAl+ga_); \
        CP16(sp_+2*TILE_B+off_, pBh+gb_); CP16(sp_+3*TILE_B+off_, pBl+gb_);} } while(0)

    const uint32_t aoff = (uint32_t)((lane & 15)*80 + (lane & 16));
    const uint32_t boff = (uint32_t)((((lane & 16) >> 1) + (lane & 7))*80 + ((lane & 8) ? 16 : 0));

#define SUBSTEP(bw_, k16_) do { \
    const uint32_t sA_ = sbase + (bw_)*STG_B; \
    uint32_t ah_[2][4], al_[2][4], bh_[4][4], bl_[4][4]; \
    uint32_t aB_ = sA_ + aoff + (k16_)*2 + wm*32*80; \
    ldsm_x4(ah_[0], aB_);          ldsm_x4(ah_[1], aB_ + 16*80); \
    ldsm_x4(al_[0], aB_ + TILE_B); ldsm_x4(al_[1], aB_ + TILE_B + 16*80); \
    uint32_t bB_ = sA_ + 2*TILE_B + boff + (k16_)*2 + wn*64*80; \
    _Pragma("unroll") \
    for (int n2_=0;n2_<4;n2_++){ ldsm_x4(bh_[n2_], bB_ + n2_*16*80); \
                                 ldsm_x4(bl_[n2_], bB_ + TILE_B + n2_*16*80);} \
    _Pragma("unroll") \
    for (int mf_=0;mf_<2;mf_++) \
        _Pragma("unroll") \
        for (int nf_=0;nf_<8;nf_++){ \
            uint32_t b0_=bh_[nf_>>1][(nf_&1)*2], b1_=bh_[nf_>>1][(nf_&1)*2+1]; \
            uint32_t c0_=bl_[nf_>>1][(nf_&1)*2], c1_=bl_[nf_>>1][(nf_&1)*2+1]; \
            mma16816(acc[mf_][nf_], ah_[mf_], b0_, b1_); \
            mma16816(acc[mf_][nf_], ah_[mf_], c0_, c1_); \
            mma16816(acc[mf_][nf_], al_[mf_], b0_, b1_);} } while(0)

    const int tiles = K >> 5;
    ISSUED(0, 0);  CP_COMMIT();
    ISSUED(32, 1); CP_COMMIT();

    for (int t = 0; t < tiles; t++) {
        CP_WAIT1();
        __syncthreads();
        SUBSTEP(t & 1, 0);
        SUBSTEP(t & 1, 16);
        __syncthreads();
        if (t + 2 < tiles) ISSUED((t + 2) * 32, t & 1);
        CP_COMMIT();
    }
#undef ISSUED
#undef SUBSTEP

#pragma unroll
    for (int mf = 0; mf < 2; mf++) {
#pragma unroll
        for (int nf = 0; nf < 8; nf++) {
            const int row = m0 + wm*32 + mf*16 + rr;
            const int col = n0 + wn*64 + nf*8 + kc;
            float b0 = bias[col], b1 = bias[col+1];
            float v0 = acc[mf][nf][0]+b0, v1 = acc[mf][nf][1]+b1;
            float v2 = acc[mf][nf][2]+b0, v3 = acc[mf][nf][3]+b1;
            if (EPI == 5) {
                v0 = 0.5f*v0*(1.0f+erff(v0*0.70710678118654752f));
                v1 = 0.5f*v1*(1.0f+erff(v1*0.70710678118654752f));
                v2 = 0.5f*v2*(1.0f+erff(v2*0.70710678118654752f));
                v3 = 0.5f*v3*(1.0f+erff(v3*0.70710678118654752f));
            }
            if (EPI == 0) {
                *(float2*)(C + (size_t)row*cRS + col)     = make_float2(v0, v1);
                *(float2*)(C + (size_t)(row+8)*cRS + col) = make_float2(v2, v3);
            } else {
                uint32_t h01, l01, h23, l23;
                split2(v0, v1, h01, l01);
                split2(v2, v3, h23, l23);
                *(uint32_t*)(Ch + (size_t)row*cRS + col)     = h01;
                *(uint32_t*)(Ch + (size_t)(row+8)*cRS + col) = h23;
                *(uint32_t*)(Cl + (size_t)row*cRS + col)     = l01;
                *(uint32_t*)(Cl + (size_t)(row+8)*cRS + col) = l23;
            }
        }
    }
}

// ================= fused flash attention ====================================
// grid (8 m-tiles, 64 z). z = zb + 4*zh so concurrent CTAs share bias in L2.
// 3-stage cp.async K/V pipeline; bias prefetched to registers from global.
#define FQP_B 144                       // 72 bf16 pitch
#define FK_B  9216                      // 64 x 72 x 2
#define FSTG_B (4*FK_B)                 // 36864 per K/V stage
#define FQ_B  36864                     // Qh+Ql
#define FSMEM (FQ_B + 3*FSTG_B)         // 147456

__global__ void __launch_bounds__(256)
flash_attn(const __nv_bfloat16* __restrict__ qkvH, const __nv_bfloat16* __restrict__ qkvL,
           const float* __restrict__ attnbias,
           __nv_bfloat16* __restrict__ Ch, __nv_bfloat16* __restrict__ Cl)
{
    extern __shared__ char smc[];
    const uint32_t sbase = (uint32_t)__cvta_generic_to_shared(smc);
    const int tid = threadIdx.x, wid = tid >> 5, lane = tid & 31;
    const int m0 = blockIdx.x * 128;
    const int z = blockIdx.y, zb = z & 3, zh = z >> 2;
    const int rr = lane >> 2, kc = (lane & 3) * 2;

    const size_t qbase = (size_t)zb * SEQ * 3072 + (size_t)zh * 64;
    const __nv_bfloat16* gQh = qkvH + qbase;
    const __nv_bfloat16* gQl = qkvL + qbase;
    const __nv_bfloat16* gKh = qkvH + qbase + DMODEL;
    const __nv_bfloat16* gKl = qkvL + qbase + DMODEL;
    const __nv_bfloat16* gVh = qkvH + qbase + 2*DMODEL;
    const __nv_bfloat16* gVl = qkvL + qbase + 2*DMODEL;
    const float* gB = attnbias + (size_t)zh * SEQ * SEQ + (size_t)m0 * SEQ;

#define ISSUE(j_) do { \
    const uint32_t sb_ = sbase + FQ_B + ((j_)%3)*FSTG_B; \
    const int s0_ = (j_)*64; \
    _Pragma("unroll") \
    for (int it_=0; it_<8; it_++){ int i_ = tid + it_*256; \
        int t_ = i_ >> 9; int idx_ = i_ & 511; int row_ = idx_>>3, seg_ = idx_&7; \
        const __nv_bfloat16* s_; \
        if (t_==0) s_ = gKh; else if (t_==1) s_ = gKl; \
        else if (t_==2) s_ = gVh; else s_ = gVl; \
        CP16(sb_ + t_*FK_B + row_*FQP_B + seg_*16, \
             s_ + (size_t)(s0_+row_)*3072 + seg_*8); } } while (0)

    ISSUE(0); CP_COMMIT();
    ISSUE(1); CP_COMMIT();
    ISSUE(2); CP_COMMIT();

    // Q tile load (plain): 128 x 64 h/l, pitch 72
    for (int i = tid; i < 2048; i += 256) {
        int t = i >> 10, idx = i & 1023, row = idx >> 3, seg = idx & 7;
        const __nv_bfloat16* s = t ? gQl : gQh;
        uint4 v = *(const uint4*)(s + (size_t)(m0+row)*3072 + seg*8);
        *(uint4*)(smc + t*18432 + row*FQP_B + seg*16) = v;
    }
    __syncthreads();

    // preload Q fragments
    const uint32_t aoff = (uint32_t)((lane & 15)*FQP_B + (lane & 16));
    uint32_t qh[4][4], ql[4][4];
    {
        uint32_t qB = sbase + aoff + wid*16*FQP_B;
#pragma unroll
        for (int ks = 0; ks < 4; ks++) {
            ldsm_x4(qh[ks], qB + ks*32);
            ldsm_x4(ql[ks], qB + 18432 + ks*32);
        }
    }

    const uint32_t boff = (uint32_t)((((lane & 16) >> 1) + (lane & 7))*FQP_B + ((lane & 8) ? 16 : 0));
    const uint32_t voff = (uint32_t)((lane & 15)*FQP_B + (lane & 16));
    const int r0 = wid*16 + rr;

    float O[8][4];
#pragma unroll
    for (int j=0;j<8;j++)
#pragma unroll
        for (int q=0;q<4;q++) O[j][q]=0.f;
    float mrow0 = -INFINITY, mrow1 = -INFINITY, lrow0 = 0.f, lrow1 = 0.f;

    for (int j = 0; j < 16; j++) {
        // bias prefetch (independent of cp.async stages)
        float2 bq0[8], bq1[8];
#pragma unroll
        for (int nf=0;nf<8;nf++){
            bq0[nf] = *(const float2*)(gB + (size_t)r0*SEQ + j*64 + nf*8 + kc);
            bq1[nf] = *(const float2*)(gB + (size_t)(r0+8)*SEQ + j*64 + nf*8 + kc);
        }

        CP_WAIT2();
        __syncthreads();

        const uint32_t stg = sbase + FQ_B + (j%3)*FSTG_B;

        // ---- S = Q @ K^T (3-term split) ----
        float s[8][4];
#pragma unroll
        for (int nf=0;nf<8;nf++)
#pragma unroll
            for (int q=0;q<4;q++) s[nf][q]=0.f;
#pragma unroll
        for (int ks = 0; ks < 4; ks++) {
            uint32_t kh[4][4], kl[4][4];
            uint32_t kB = stg + boff + ks*32;
#pragma unroll
            for (int nb=0;nb<4;nb++){
                ldsm_x4(kh[nb], kB + nb*16*FQP_B);
                ldsm_x4(kl[nb], kB + FK_B + nb*16*FQP_B);
            }
#pragma unroll
            for (int nf=0;nf<8;nf++){
                uint32_t b0=kh[nf>>1][(nf&1)*2], b1=kh[nf>>1][(nf&1)*2+1];
                uint32_t c0=kl[nf>>1][(nf&1)*2], c1=kl[nf>>1][(nf&1)*2+1];
                mma16816(s[nf], qh[ks], b0, b1);
                mma16816(s[nf], qh[ks], c0, c1);
                mma16816(s[nf], ql[ks], b0, b1);
            }
        }

        // ---- scale + bias (registers) ----
#pragma unroll
        for (int nf=0;nf<8;nf++){
            s[nf][0] = fmaf(s[nf][0], 0.125f, bq0[nf].x);
            s[nf][1] = fmaf(s[nf][1], 0.125f, bq0[nf].y);
            s[nf][2] = fmaf(s[nf][2], 0.125f, bq1[nf].x);
            s[nf][3] = fmaf(s[nf][3], 0.125f, bq1[nf].y);
        }

        // ---- online softmax ----
        float mx0 = -INFINITY, mx1 = -INFINITY;
#pragma unroll
        for (int nf=0;nf<8;nf++){
            mx0 = fmaxf(mx0, fmaxf(s[nf][0], s[nf][1]));
            mx1 = fmaxf(mx1, fmaxf(s[nf][2], s[nf][3]));
        }
        mx0 = fmaxf(mx0, __shfl_xor_sync(0xffffffffu, mx0, 1));
        mx0 = fmaxf(mx0, __shfl_xor_sync(0xffffffffu, mx0, 2));
        mx1 = fmaxf(mx1, __shfl_xor_sync(0xffffffffu, mx1, 1));
        mx1 = fmaxf(mx1, __shfl_xor_sync(0xffffffffu, mx1, 2));
        float mn0 = fmaxf(mrow0, mx0), mn1 = fmaxf(mrow1, mx1);
        float a0 = exp2f((mrow0 - mn0)*LOG2E), a1 = exp2f((mrow1 - mn1)*LOG2E);
        mrow0 = mn0; mrow1 = mn1;

        float rs0 = 0.f, rs1 = 0.f;
#pragma unroll
        for (int nf=0;nf<8;nf++){
            s[nf][0] = exp2f((s[nf][0]-mn0)*LOG2E);
            s[nf][1] = exp2f((s[nf][1]-mn0)*LOG2E);
            s[nf][2] = exp2f((s[nf][2]-mn1)*LOG2E);
            s[nf][3] = exp2f((s[nf][3]-mn1)*LOG2E);
            rs0 += s[nf][0] + s[nf][1];
            rs1 += s[nf][2] + s[nf][3];
        }
        lrow0 = lrow0*a0 + rs0;
        lrow1 = lrow1*a1 + rs1;

        // ---- pack P into A fragments (hi/lo) ----
        uint32_t ph[4][4], pl[4][4];
#pragma unroll
        for (int ks=0;ks<4;ks++){
            const float* pe = s[2*ks];
            const float* po = s[2*ks+1];
            split2(pe[0], pe[1], ph[ks][0], pl[ks][0]);
            split2(pe[2], pe[3], ph[ks][1], pl[ks][1]);
            split2(po[0], po[1], ph[ks][2], pl[ks][2]);
            split2(po[2], po[3], ph[ks][3], pl[ks][3]);
        }

        // ---- O = O*alpha + P @ V ----
#pragma unroll
        for (int nf=0;nf<8;nf++){
            O[nf][0] *= a0; O[nf][1] *= a0;
            O[nf][2] *= a1; O[nf][3] *= a1;
        }
#pragma unroll
        for (int ks = 0; ks < 4; ks++) {
            uint32_t vh[4][4], vl[4][4];
            uint32_t vB = stg + 2*FK_B + voff + ks*16*FQP_B;
#pragma unroll
            for (int nb=0;nb<4;nb++){
                ldsm_x4t(vh[nb], vB + nb*32);
                ldsm_x4t(vl[nb], vB + FK_B + nb*32);
            }
#pragma unroll
            for (int nf=0;nf<8;nf++){
                uint32_t b0=vh[nf>>1][(nf&1)*2], b1=vh[nf>>1][(nf&1)*2+1];
                uint32_t c0=vl[nf>>1][(nf&1)*2], c1=vl[nf>>1][(nf&1)*2+1];
                mma16816(O[nf], ph[ks], b0, b1);
                mma16816(O[nf], ph[ks], c0, c1);
                mma16816(O[nf], pl[ks], b0, b1);
            }
        }

        __syncthreads();
        if (j + 3 < 16) ISSUE(j + 3);
        CP_COMMIT();
    }
#undef ISSUE

    // ---- finalize ----
    lrow0 += __shfl_xor_sync(0xffffffffu, lrow0, 1);
    lrow0 += __shfl_xor_sync(0xffffffffu, lrow0, 2);
    lrow1 += __shfl_xor_sync(0xffffffffu, lrow1, 1);
    lrow1 += __shfl_xor_sync(0xffffffffu, lrow1, 2);
    const float inv0 = 1.0f / lrow0, inv1 = 1.0f / lrow1;

    const size_t row0 = (size_t)zb*SEQ + m0 + wid*16 + rr;
#pragma unroll
    for (int nf=0;nf<8;nf++){
        const int col = zh*64 + nf*8 + kc;
        uint32_t h01, l01, h23, l23;
        split2(O[nf][0]*inv0, O[nf][1]*inv0, h01, l01);
        split2(O[nf][2]*inv1, O[nf][3]*inv1, h23, l23);
        *(uint32_t*)(Ch + row0*DMODEL + col)     = h01;
        *(uint32_t*)(Ch + (row0+8)*DMODEL + col) = h23;
        *(uint32_t*)(Cl + row0*DMODEL + col)     = l01;
        *(uint32_t*)(Cl + (row0+8)*DMODEL + col) = l23;
    }
}

// ================= fp32 -> bf16 hi/lo split ==================================
__global__ void __launch_bounds__(256)
split_kernel(const float* __restrict__ in, __nv_bfloat16* __restrict__ hi,
             __nv_bfloat16* __restrict__ lo)
{
    const size_t i4 = ((size_t)blockIdx.x * 256 + threadIdx.x) * 4;
    float4 v = *(const float4*)(in + i4);
    uint32_t h01, l01, h23, l23;
    split2(v.x, v.y, h01, l01);
    split2(v.z, v.w, h23, l23);
    *(uint32_t*)(hi + i4)     = h01;
    *(uint32_t*)(hi + i4 + 2) = h23;
    *(uint32_t*)(lo + i4)     = l01;
    *(uint32_t*)(lo + i4 + 2) = l23;
}

// ---------------- residual add + LayerNorm (optional fused split) ------------
__device__ __forceinline__ float warpSum(float v) {
#pragma unroll
    for (int o = 16; o; o >>= 1) v += __shfl_xor_sync(0xffffffffu, v, o);
    return v;
}

template<bool SPLIT>
__global__ void __launch_bounds__(256)
add_ln_kernel(const float* __restrict__ a, const float* __restrict__ b,
              const float* __restrict__ gamma, const float* __restrict__ beta,
              float* __restrict__ out,
              __nv_bfloat16* __restrict__ oh, __nv_bfloat16* __restrict__ ol)
{
    const size_t base = (size_t)blockIdx.x * DMODEL;
    const int tid = threadIdx.x;
    __shared__ float sh[8];

    float4 av = *(const float4*)(a + base + tid * 4);
    float4 bv = *(const float4*)(b + base + tid * 4);
    float v[4] = {av.x + bv.x, av.y + bv.y, av.z + bv.z, av.w + bv.w};

    float s = v[0] + v[1] + v[2] + v[3];
    s = warpSum(s);
    if ((tid & 31) == 0) sh[tid >> 5] = s;
    __syncthreads();
    if (tid < 32) {
        float t = (tid < 8) ? sh[tid] : 0.f;
        t = warpSum(t);
        if (tid == 0) sh[0] = t;
    }
    __syncthreads();
    float mu = sh[0] * (1.0f / DMODEL);
    __syncthreads();

    float sq = 0.f;
#pragma unroll
    for (int j = 0; j < 4; j++) { float d = v[j] - mu; sq += d * d; }
    sq = warpSum(sq);
    if ((tid & 31) == 0) sh[tid >> 5] = sq;
    __syncthreads();
    if (tid < 32) {
        float t = (tid < 8) ? sh[tid] : 0.f;
        t = warpSum(t);
        if (tid == 0) sh[0] = t;
    }
    __syncthreads();
    float rstd = rsqrtf(sh[0] * (1.0f / DMODEL) + EPS);

    float4 gv = *(const float4*)(gamma + tid * 4);
    float4 tv = *(const float4*)(beta + tid * 4);
    float o0 = (v[0] - mu) * rstd * gv.x + tv.x;
    float o1 = (v[1] - mu) * rstd * gv.y + tv.y;
    float o2 = (v[2] - mu) * rstd * gv.z + tv.z;
    float o3 = (v[3] - mu) * rstd * gv.w + tv.w;
    *(float4*)(out + base + tid * 4) = make_float4(o0, o1, o2, o3);
    if (SPLIT) {
        uint32_t h01, l01, h23, l23;
        split2(o0, o1, h01, l01);
        split2(o2, o3, h23, l23);
        *(uint32_t*)(oh + base + tid*4)     = h01;
        *(uint32_t*)(oh + base + tid*4 + 2) = h23;
        *(uint32_t*)(ol + base + tid*4)     = l01;
        *(uint32_t*)(ol + base + tid*4 + 2) = l23;
    }
}

// ---------------- launch ------------------------------------------------------
extern "C" void kernel_launch(void* const* d_in, const int* in_sizes, int n_in,
                              void* d_out, int out_size)
{
    const float* src      = (const float*)d_in[0];
    const float* attnbias = (const float*)d_in[1];
    const float* Wqkv     = (const float*)d_in[2];
    const float* bqkv     = (const float*)d_in[3];
    const float* Wo       = (const float*)d_in[4];
    const float* bo       = (const float*)d_in[5];
    const float* g1       = (const float*)d_in[6];
    const float* b1n      = (const float*)d_in[7];
    const float* g2       = (const float*)d_in[8];
    const float* b2n      = (const float*)d_in[9];
    const float* W1       = (const float*)d_in[10];
    const float* b1       = (const float*)d_in[11];
    const float* W2       = (const float*)d_in[12];
    const float* b2       = (const float*)d_in[13];
    float* out = (float*)d_out;

    float *attnout, *x, *ffo;
    cudaGetSymbolAddress((void**)&attnout, g_attnout);
    cudaGetSymbolAddress((void**)&x,       g_x);
    cudaGetSymbolAddress((void**)&ffo,     g_ffo);

    __nv_bfloat16 *srcH,*srcL,*qkvH,*qkvL,*ctxH,*ctxL,*xH,*xL,*ffhH,*ffhL;
    __nv_bfloat16 *WqkvH,*WqkvL,*WoH,*WoL,*W1H,*W1L,*W2H,*W2L;
    cudaGetSymbolAddress((void**)&srcH, g_srcH);   cudaGetSymbolAddress((void**)&srcL, g_srcL);
    cudaGetSymbolAddress((void**)&qkvH, g_qkvH);   cudaGetSymbolAddress((void**)&qkvL, g_qkvL);
    cudaGetSymbolAddress((void**)&ctxH, g_ctxH);   cudaGetSymbolAddress((void**)&ctxL, g_ctxL);
    cudaGetSymbolAddress((void**)&xH,   g_xH);     cudaGetSymbolAddress((void**)&xL,   g_xL);
    cudaGetSymbolAddress((void**)&ffhH, g_ffhH);   cudaGetSymbolAddress((void**)&ffhL, g_ffhL);
    cudaGetSymbolAddress((void**)&WqkvH,g_WqkvH);  cudaGetSymbolAddress((void**)&WqkvL,g_WqkvL);
    cudaGetSymbolAddress((void**)&WoH,  g_WoH);    cudaGetSymbolAddress((void**)&WoL,  g_WoL);
    cudaGetSymbolAddress((void**)&W1H,  g_W1H);    cudaGetSymbolAddress((void**)&W1L,  g_W1L);
    cudaGetSymbolAddress((void**)&W2H,  g_W2H);    cudaGetSymbolAddress((void**)&W2L,  g_W2L);

    cudaFuncSetAttribute(gemm_bf16s<0>, cudaFuncAttributeMaxDynamicSharedMemorySize, DSMEM);
    cudaFuncSetAttribute(gemm_bf16s<4>, cudaFuncAttributeMaxDynamicSharedMemorySize, DSMEM);
    cudaFuncSetAttribute(gemm_bf16s<5>, cudaFuncAttributeMaxDynamicSharedMemorySize, DSMEM);
    cudaFuncSetAttribute(flash_attn,    cudaFuncAttributeMaxDynamicSharedMemorySize, FSMEM);

    dim3 blk(256);

    // operand splits
    split_kernel<<<MS*DMODEL/1024, blk>>>(src,  srcH, srcL);
    split_kernel<<<3*DMODEL*DMODEL/1024, blk>>>(Wqkv, WqkvH, WqkvL);
    split_kernel<<<DMODEL*DMODEL/1024, blk>>>(Wo,   WoH,   WoL);
    split_kernel<<<FFDIM*DMODEL/1024, blk>>>(W1,   W1H,   W1L);
    split_kernel<<<DMODEL*FFDIM/1024, blk>>>(W2,   W2H,   W2L);

    // 1) QKV = src @ Wqkv^T + bqkv -> split qkvH/L
    gemm_bf16s<4><<<dim3(24, 32), blk, DSMEM>>>(
        srcH, srcL, WqkvH, WqkvL, nullptr, qkvH, qkvL,
        DMODEL, 3072, DMODEL, DMODEL, bqkv);

    // 2-4) fused attention -> split ctxH/L
    flash_attn<<<dim3(8, 64), blk, FSMEM>>>(qkvH, qkvL, attnbias, ctxH, ctxL);

    // 5) attn_out = ctx @ Wo^T + bo
    gemm_bf16s<0><<<dim3(8, 32), blk, DSMEM>>>(
        ctxH, ctxL, WoH, WoL, attnout, nullptr, nullptr,
        DMODEL, DMODEL, DMODEL, DMODEL, bo);

    // 6) x = LN(src + attn_out)  (+ fused split)
    add_ln_kernel<true><<<MS, blk>>>(src, attnout, g1, b1n, x, xH, xL);

    // 7) ffh = gelu(x @ W1^T + b1) -> split ffhH/L
    gemm_bf16s<5><<<dim3(32, 32), blk, DSMEM>>>(
        xH, xL, W1H, W1L, nullptr, ffhH, ffhL,
        DMODEL, FFDIM, DMODEL, DMODEL, b1);

    // 8) ffo = ffh @ W2^T + b2
    gemm_bf16s<0><<<dim3(8, 32), blk, DSMEM>>>(
        ffhH, ffhL, W2H, W2L, ffo, nullptr, nullptr,
        FFDIM, DMODEL, FFDIM, FFDIM, b2);

    // 9) out = LN(x + ffo)
    add_ln_kernel<false><<<MS, blk>>>(x, ffo, g2, b2n, out, nullptr, nullptr);
}